// round 1
// baseline (speedup 1.0000x reference)
#include <cuda_runtime.h>
#include <math.h>

#define DIMW 3072
#define NH 24
#define HD 128
#define TXT_N 512
#define REF_N 512
#define STOT_N 2560
#define SHID_N 2048

// ---- scratch (device globals; no allocations allowed) ----
__device__ float g_q[STOT_N * DIMW];
__device__ float g_k[STOT_N * DIMW];
__device__ float g_v[STOT_N * DIMW];
__device__ float g_o[STOT_N * DIMW];

// ---- helpers ----
__device__ __forceinline__ unsigned f2t(float f) {
    unsigned u; asm("cvt.rna.tf32.f32 %0, %1;" : "=r"(u) : "f"(f)); return u;
}

__device__ __forceinline__ void mma8(float* c, unsigned a0, unsigned a1, unsigned a2, unsigned a3,
                                     unsigned b0, unsigned b1) {
    asm volatile("mma.sync.aligned.m16n8k8.row.col.f32.tf32.tf32.f32 "
        "{%0,%1,%2,%3}, {%4,%5,%6,%7}, {%8,%9}, {%0,%1,%2,%3};\n"
        : "+f"(c[0]), "+f"(c[1]), "+f"(c[2]), "+f"(c[3])
        : "r"(a0), "r"(a1), "r"(a2), "r"(a3), "r"(b0), "r"(b1));
}

// ============================================================================
// GEMM: C[M,3072] = A[M,3072] @ W[3072,3072] + bias, split-tf32 (3 MMA) for
// near-fp32 accuracy. BM=BN=128, BK=16. 256 threads = 8 warps (4m x 2n),
// warp tile 32x64, m16n8k8 tiles 2x8.
// ============================================================================
__global__ void __launch_bounds__(256) gemm3072(const float* __restrict__ A,
        const float* __restrict__ W, const float* __restrict__ bias,
        float* __restrict__ C)
{
    __shared__ unsigned sAh[128][17];
    __shared__ unsigned sAl[128][17];
    __shared__ unsigned sBh[16][132];
    __shared__ unsigned sBl[16][132];

    const int tid  = threadIdx.x;
    const int lane = tid & 31;
    const int warp = tid >> 5;
    const int wm = warp >> 1;      // 0..3
    const int wn = warp & 1;       // 0..1
    const int mBase = blockIdx.y * 128;
    const int nBase = blockIdx.x * 128;

    float acc[2][8][4];
    #pragma unroll
    for (int i = 0; i < 2; i++)
        #pragma unroll
        for (int j = 0; j < 8; j++)
            #pragma unroll
            for (int p = 0; p < 4; p++) acc[i][j][p] = 0.f;

    for (int kb = 0; kb < DIMW / 16; kb++) {
        // A tile 128x16
        #pragma unroll
        for (int i = 0; i < 2; i++) {
            int f = tid + i * 256;
            int row = f >> 2, c4 = f & 3;
            const float4 v4 = *(const float4*)(A + (size_t)(mBase + row) * DIMW + kb * 16 + c4 * 4);
            float vv[4] = {v4.x, v4.y, v4.z, v4.w};
            #pragma unroll
            for (int j = 0; j < 4; j++) {
                unsigned h = f2t(vv[j]);
                sAh[row][c4 * 4 + j] = h;
                sAl[row][c4 * 4 + j] = f2t(vv[j] - __uint_as_float(h));
            }
        }
        // B tile 16x128
        #pragma unroll
        for (int i = 0; i < 2; i++) {
            int f = tid + i * 256;
            int row = f >> 5, c4 = f & 31;
            const float4 v4 = *(const float4*)(W + (size_t)(kb * 16 + row) * DIMW + nBase + c4 * 4);
            float vv[4] = {v4.x, v4.y, v4.z, v4.w};
            #pragma unroll
            for (int j = 0; j < 4; j++) {
                unsigned h = f2t(vv[j]);
                sBh[row][c4 * 4 + j] = h;
                sBl[row][c4 * 4 + j] = f2t(vv[j] - __uint_as_float(h));
            }
        }
        __syncthreads();
        #pragma unroll
        for (int ks = 0; ks < 2; ks++) {
            const int kc = ks * 8 + (lane & 3);
            unsigned ah[2][4], al[2][4];
            #pragma unroll
            for (int mt = 0; mt < 2; mt++) {
                int r = wm * 32 + mt * 16 + (lane >> 2);
                ah[mt][0] = sAh[r][kc];     ah[mt][1] = sAh[r + 8][kc];
                ah[mt][2] = sAh[r][kc + 4]; ah[mt][3] = sAh[r + 8][kc + 4];
                al[mt][0] = sAl[r][kc];     al[mt][1] = sAl[r + 8][kc];
                al[mt][2] = sAl[r][kc + 4]; al[mt][3] = sAl[r + 8][kc + 4];
            }
            #pragma unroll
            for (int nt = 0; nt < 8; nt++) {
                int cn = wn * 64 + nt * 8 + (lane >> 2);
                unsigned bh0 = sBh[ks * 8 + (lane & 3)][cn];
                unsigned bh1 = sBh[ks * 8 + (lane & 3) + 4][cn];
                unsigned bl0 = sBl[ks * 8 + (lane & 3)][cn];
                unsigned bl1 = sBl[ks * 8 + (lane & 3) + 4][cn];
                #pragma unroll
                for (int mt = 0; mt < 2; mt++) {
                    mma8(acc[mt][nt], ah[mt][0], ah[mt][1], ah[mt][2], ah[mt][3], bh0, bh1);
                    mma8(acc[mt][nt], ah[mt][0], ah[mt][1], ah[mt][2], ah[mt][3], bl0, bl1);
                    mma8(acc[mt][nt], al[mt][0], al[mt][1], al[mt][2], al[mt][3], bh0, bh1);
                }
            }
        }
        __syncthreads();
    }
    // epilogue
    #pragma unroll
    for (int mt = 0; mt < 2; mt++) {
        int r = mBase + wm * 32 + mt * 16 + (lane >> 2);
        #pragma unroll
        for (int nt = 0; nt < 8; nt++) {
            int cgl = nBase + wn * 64 + nt * 8 + (lane & 3) * 2;
            float b0 = bias[cgl], b1 = bias[cgl + 1];
            C[(size_t)r * DIMW + cgl]           = acc[mt][nt][0] + b0;
            C[(size_t)r * DIMW + cgl + 1]       = acc[mt][nt][1] + b1;
            C[(size_t)(r + 8) * DIMW + cgl]     = acc[mt][nt][2] + b0;
            C[(size_t)(r + 8) * DIMW + cgl + 1] = acc[mt][nt][3] + b1;
        }
    }
}

// ============================================================================
// Fused per-head RMSNorm + interleaved RoPE, in place on q and k.
// 1 warp = 1 (token, head). txt tokens (<512) use naq/nak; rest use nq/nk.
// ============================================================================
__global__ void __launch_bounds__(128) norm_rope(float* __restrict__ q, float* __restrict__ k,
        const float* __restrict__ nq, const float* __restrict__ nk,
        const float* __restrict__ naq, const float* __restrict__ nak,
        const float* __restrict__ rc, const float* __restrict__ rs)
{
    const int gw   = blockIdx.x * 4 + (threadIdx.x >> 5);
    const int lane = threadIdx.x & 31;
    const int t = gw / NH, h = gw % NH;
    const size_t base = (size_t)t * DIMW + h * HD + lane * 4;
    const float* wq = (t < TXT_N) ? naq : nq;
    const float* wk = (t < TXT_N) ? nak : nk;
    const float4 c4 = *(const float4*)(rc + (size_t)t * HD + lane * 4);
    const float4 s4 = *(const float4*)(rs + (size_t)t * HD + lane * 4);

    #pragma unroll
    for (int which = 0; which < 2; which++) {
        float* buf = which ? k : q;
        const float* wv = which ? wk : wq;
        float4 x = *(float4*)(buf + base);
        float ss = x.x * x.x + x.y * x.y + x.z * x.z + x.w * x.w;
        ss += __shfl_xor_sync(0xffffffffu, ss, 16);
        ss += __shfl_xor_sync(0xffffffffu, ss, 8);
        ss += __shfl_xor_sync(0xffffffffu, ss, 4);
        ss += __shfl_xor_sync(0xffffffffu, ss, 2);
        ss += __shfl_xor_sync(0xffffffffu, ss, 1);
        float r = rsqrtf(ss * (1.0f / HD) + 1e-6f);
        float4 w4 = *(const float4*)(wv + lane * 4);
        x.x *= r * w4.x; x.y *= r * w4.y; x.z *= r * w4.z; x.w *= r * w4.w;
        float4 y;
        y.x = x.x * c4.x - x.y * s4.x;
        y.y = x.y * c4.y + x.x * s4.y;
        y.z = x.z * c4.z - x.w * s4.z;
        y.w = x.w * c4.w + x.z * s4.w;
        *(float4*)(buf + base) = y;
    }
}

// ============================================================================
// Flash attention. Grid (40 q-tiles of 64, 24 heads). 128 threads = 4 warps,
// warp owns 16 q-rows. Q,K split-tf32 (3 MMA QK^T), V/P single tf32 (1 MMA PV).
// ref q-tiles (tokens [512,1024)) attend only to kv [512,1024); others to all.
// ============================================================================
__global__ void __launch_bounds__(128) flash(const float* __restrict__ q,
        const float* __restrict__ k, const float* __restrict__ v, float* __restrict__ o)
{
    extern __shared__ unsigned sm[];
    unsigned* Qh = sm;
    unsigned* Ql = Qh + 64 * 132;
    unsigned* Kh = Ql + 64 * 132;
    unsigned* Kl = Kh + 64 * 132;
    unsigned* Vs = Kl + 64 * 132;
    unsigned* Ps = Vs + 64 * 132;   // 64 x 68

    const int tid = threadIdx.x, lane = tid & 31, w = tid >> 5;
    const int qt = blockIdx.x, h = blockIdx.y;
    const int qb = qt * 64;
    const bool isref = (qb >= TXT_N) && (qb < TXT_N + REF_N);
    const int kv0 = isref ? TXT_N : 0;
    const int nkt = isref ? (REF_N / 64) : (STOT_N / 64);

    // load Q tile (64x128), split hi/lo
    #pragma unroll
    for (int i = 0; i < 16; i++) {
        int f = tid + i * 128;
        int row = f >> 5, d4 = f & 31;
        float4 x = *(const float4*)(q + (size_t)(qb + row) * DIMW + h * HD + d4 * 4);
        float vv[4] = {x.x, x.y, x.z, x.w};
        #pragma unroll
        for (int j = 0; j < 4; j++) {
            unsigned hh = f2t(vv[j]);
            Qh[row * 132 + d4 * 4 + j] = hh;
            Ql[row * 132 + d4 * 4 + j] = f2t(vv[j] - __uint_as_float(hh));
        }
    }

    float O[16][4];
    #pragma unroll
    for (int i = 0; i < 16; i++)
        #pragma unroll
        for (int j = 0; j < 4; j++) O[i][j] = 0.f;
    float m0 = -1e30f, m1 = -1e30f, l0 = 0.f, l1 = 0.f;
    const int r0 = w * 16 + (lane >> 2);

    for (int it = 0; it < nkt; it++) {
        __syncthreads();
        const int kt0 = kv0 + it * 64;
        #pragma unroll
        for (int i = 0; i < 16; i++) {
            int f = tid + i * 128;
            int row = f >> 5, d4 = f & 31;
            float4 x = *(const float4*)(k + (size_t)(kt0 + row) * DIMW + h * HD + d4 * 4);
            float vv[4] = {x.x, x.y, x.z, x.w};
            #pragma unroll
            for (int j = 0; j < 4; j++) {
                unsigned hh = f2t(vv[j]);
                Kh[row * 132 + d4 * 4 + j] = hh;
                Kl[row * 132 + d4 * 4 + j] = f2t(vv[j] - __uint_as_float(hh));
            }
            float4 y = *(const float4*)(v + (size_t)(kt0 + row) * DIMW + h * HD + d4 * 4);
            Vs[row * 132 + d4 * 4 + 0] = f2t(y.x);
            Vs[row * 132 + d4 * 4 + 1] = f2t(y.y);
            Vs[row * 132 + d4 * 4 + 2] = f2t(y.z);
            Vs[row * 132 + d4 * 4 + 3] = f2t(y.w);
        }
        __syncthreads();

        // S = Q @ K^T  (split: hi*hi + hi*lo + lo*hi)
        float s[8][4];
        #pragma unroll
        for (int i = 0; i < 8; i++)
            #pragma unroll
            for (int j = 0; j < 4; j++) s[i][j] = 0.f;
        #pragma unroll
        for (int ks = 0; ks < 16; ks++) {
            const int kc = ks * 8 + (lane & 3);
            unsigned a0 = Qh[r0 * 132 + kc],     a1 = Qh[(r0 + 8) * 132 + kc];
            unsigned a2 = Qh[r0 * 132 + kc + 4], a3 = Qh[(r0 + 8) * 132 + kc + 4];
            unsigned e0 = Ql[r0 * 132 + kc],     e1 = Ql[(r0 + 8) * 132 + kc];
            unsigned e2 = Ql[r0 * 132 + kc + 4], e3 = Ql[(r0 + 8) * 132 + kc + 4];
            #pragma unroll
            for (int nt = 0; nt < 8; nt++) {
                int bn = nt * 8 + (lane >> 2);
                unsigned bh0 = Kh[bn * 132 + kc], bh1 = Kh[bn * 132 + kc + 4];
                unsigned bl0 = Kl[bn * 132 + kc], bl1 = Kl[bn * 132 + kc + 4];
                mma8(s[nt], a0, a1, a2, a3, bh0, bh1);
                mma8(s[nt], a0, a1, a2, a3, bl0, bl1);
                mma8(s[nt], e0, e1, e2, e3, bh0, bh1);
            }
        }
        // online softmax
        const float sc = 0.08838834764831845f;  // 1/sqrt(128)
        float rm0 = -1e30f, rm1 = -1e30f;
        #pragma unroll
        for (int nt = 0; nt < 8; nt++) {
            s[nt][0] *= sc; s[nt][1] *= sc; s[nt][2] *= sc; s[nt][3] *= sc;
            rm0 = fmaxf(rm0, fmaxf(s[nt][0], s[nt][1]));
            rm1 = fmaxf(rm1, fmaxf(s[nt][2], s[nt][3]));
        }
        rm0 = fmaxf(rm0, __shfl_xor_sync(0xffffffffu, rm0, 1));
        rm0 = fmaxf(rm0, __shfl_xor_sync(0xffffffffu, rm0, 2));
        rm1 = fmaxf(rm1, __shfl_xor_sync(0xffffffffu, rm1, 1));
        rm1 = fmaxf(rm1, __shfl_xor_sync(0xffffffffu, rm1, 2));
        float mn0 = fmaxf(m0, rm0), mn1 = fmaxf(m1, rm1);
        float al0 = __expf(m0 - mn0), al1 = __expf(m1 - mn1);
        float rs0 = 0.f, rs1 = 0.f;
        #pragma unroll
        for (int nt = 0; nt < 8; nt++) {
            s[nt][0] = __expf(s[nt][0] - mn0); s[nt][1] = __expf(s[nt][1] - mn0);
            s[nt][2] = __expf(s[nt][2] - mn1); s[nt][3] = __expf(s[nt][3] - mn1);
            rs0 += s[nt][0] + s[nt][1];
            rs1 += s[nt][2] + s[nt][3];
        }
        rs0 += __shfl_xor_sync(0xffffffffu, rs0, 1);
        rs0 += __shfl_xor_sync(0xffffffffu, rs0, 2);
        rs1 += __shfl_xor_sync(0xffffffffu, rs1, 1);
        rs1 += __shfl_xor_sync(0xffffffffu, rs1, 2);
        l0 = l0 * al0 + rs0; l1 = l1 * al1 + rs1;
        m0 = mn0; m1 = mn1;
        #pragma unroll
        for (int nt = 0; nt < 16; nt++) {
            O[nt][0] *= al0; O[nt][1] *= al0; O[nt][2] *= al1; O[nt][3] *= al1;
        }
        // P -> smem (tf32), C-layout to A-layout via smem
        #pragma unroll
        for (int nt = 0; nt < 8; nt++) {
            int pc = nt * 8 + (lane & 3) * 2;
            Ps[r0 * 68 + pc]           = f2t(s[nt][0]);
            Ps[r0 * 68 + pc + 1]       = f2t(s[nt][1]);
            Ps[(r0 + 8) * 68 + pc]     = f2t(s[nt][2]);
            Ps[(r0 + 8) * 68 + pc + 1] = f2t(s[nt][3]);
        }
        __syncwarp();
        // O += P @ V
        #pragma unroll
        for (int ks = 0; ks < 8; ks++) {
            const int pc = ks * 8 + (lane & 3);
            unsigned p0 = Ps[r0 * 68 + pc],     p1 = Ps[(r0 + 8) * 68 + pc];
            unsigned p2 = Ps[r0 * 68 + pc + 4], p3 = Ps[(r0 + 8) * 68 + pc + 4];
            #pragma unroll
            for (int nt = 0; nt < 16; nt++) {
                int vn = nt * 8 + (lane >> 2);
                unsigned vb0 = Vs[(ks * 8 + (lane & 3)) * 132 + vn];
                unsigned vb1 = Vs[(ks * 8 + (lane & 3) + 4) * 132 + vn];
                mma8(O[nt], p0, p1, p2, p3, vb0, vb1);
            }
        }
    }
    const float i0 = 1.f / l0, i1 = 1.f / l1;
    const int tok0 = qb + r0;
    #pragma unroll
    for (int nt = 0; nt < 16; nt++) {
        int col = h * HD + nt * 8 + (lane & 3) * 2;
        o[(size_t)tok0 * DIMW + col]           = O[nt][0] * i0;
        o[(size_t)tok0 * DIMW + col + 1]       = O[nt][1] * i0;
        o[(size_t)(tok0 + 8) * DIMW + col]     = O[nt][2] * i1;
        o[(size_t)(tok0 + 8) * DIMW + col + 1] = O[nt][3] * i1;
    }
}

static const int FLASH_SMEM = (5 * 64 * 132 + 64 * 68) * 4;  // 186368 B

extern "C" void kernel_launch(void* const* d_in, const int* in_sizes, int n_in,
                              void* d_out, int out_size) {
    const float* hs  = (const float*)d_in[0];
    const float* enc = (const float*)d_in[1];
    const float* rc  = (const float*)d_in[2];
    const float* rs  = (const float*)d_in[3];
    const float* wq  = (const float*)d_in[4];
    const float* bq  = (const float*)d_in[5];
    const float* wk  = (const float*)d_in[6];
    const float* bk  = (const float*)d_in[7];
    const float* wv  = (const float*)d_in[8];
    const float* bv  = (const float*)d_in[9];
    const float* waq = (const float*)d_in[10];
    const float* baq = (const float*)d_in[11];
    const float* wak = (const float*)d_in[12];
    const float* bak = (const float*)d_in[13];
    const float* wav = (const float*)d_in[14];
    const float* bav = (const float*)d_in[15];
    const float* nq  = (const float*)d_in[16];
    const float* nk  = (const float*)d_in[17];
    const float* naq = (const float*)d_in[18];
    const float* nak = (const float*)d_in[19];
    const float* wo  = (const float*)d_in[20];
    const float* bo  = (const float*)d_in[21];
    const float* wao = (const float*)d_in[22];
    const float* bao = (const float*)d_in[23];
    float* out = (float*)d_out;

    float *qp, *kp, *vp, *op;
    cudaGetSymbolAddress((void**)&qp, g_q);
    cudaGetSymbolAddress((void**)&kp, g_k);
    cudaGetSymbolAddress((void**)&vp, g_v);
    cudaGetSymbolAddress((void**)&op, g_o);

    cudaFuncSetAttribute(flash, cudaFuncAttributeMaxDynamicSharedMemorySize, FLASH_SMEM);

    dim3 g16(24, 16), g4(24, 4);
    // QKV projections: hidden tokens -> rows [512, 2560), encoder -> rows [0, 512)
    gemm3072<<<g16, 256>>>(hs,  wq,  bq,  qp + (size_t)TXT_N * DIMW);
    gemm3072<<<g16, 256>>>(hs,  wk,  bk,  kp + (size_t)TXT_N * DIMW);
    gemm3072<<<g16, 256>>>(hs,  wv,  bv,  vp + (size_t)TXT_N * DIMW);
    gemm3072<<<g4,  256>>>(enc, waq, baq, qp);
    gemm3072<<<g4,  256>>>(enc, wak, bak, kp);
    gemm3072<<<g4,  256>>>(enc, wav, bav, vp);

    norm_rope<<<STOT_N * NH / 4, 128>>>(qp, kp, nq, nk, naq, nak, rc, rs);

    flash<<<dim3(STOT_N / 64, NH), 128, FLASH_SMEM>>>(qp, kp, vp, op);

    // output projections: hs_out first (2048 rows), then enc_out (512 rows)
    gemm3072<<<g16, 256>>>(op + (size_t)TXT_N * DIMW, wo,  bo,  out);
    gemm3072<<<g4,  256>>>(op,                        wao, bao, out + (size_t)SHID_N * DIMW);
}

// round 2
// speedup vs baseline: 1.5015x; 1.5015x over previous
#include <cuda_runtime.h>
#include <math.h>

#define DIMW 3072
#define NH 24
#define HD 128
#define TXT_N 512
#define REF_N 512
#define STOT_N 2560
#define SHID_N 2048
#define WELTS (DIMW * DIMW)

// ---- scratch (device globals; no allocations allowed) ----
__device__ float g_q[STOT_N * DIMW];
__device__ float g_k[STOT_N * DIMW];
__device__ float g_v[STOT_N * DIMW];
__device__ float g_o[STOT_N * DIMW];
// tf32 hi/lo pre-split scratch
__device__ unsigned g_ah[STOT_N * DIMW];
__device__ unsigned g_al[STOT_N * DIMW];
__device__ unsigned g_wh[8ull * WELTS];
__device__ unsigned g_wl[8ull * WELTS];

// ---- helpers ----
__device__ __forceinline__ unsigned f2t(float f) {
    unsigned u; asm("cvt.rna.tf32.f32 %0, %1;" : "=r"(u) : "f"(f)); return u;
}

__device__ __forceinline__ void mma8(float* c, unsigned a0, unsigned a1, unsigned a2, unsigned a3,
                                     unsigned b0, unsigned b1) {
    asm volatile("mma.sync.aligned.m16n8k8.row.col.f32.tf32.tf32.f32 "
        "{%0,%1,%2,%3}, {%4,%5,%6,%7}, {%8,%9}, {%0,%1,%2,%3};\n"
        : "+f"(c[0]), "+f"(c[1]), "+f"(c[2]), "+f"(c[3])
        : "r"(a0), "r"(a1), "r"(a2), "r"(a3), "r"(b0), "r"(b1));
}

__device__ __forceinline__ void cpa16(unsigned saddr, const void* g) {
    asm volatile("cp.async.ca.shared.global [%0], [%1], 16;\n" :: "r"(saddr), "l"(g));
}
__device__ __forceinline__ void cpa_commit() { asm volatile("cp.async.commit_group;\n"); }

// ============================================================================
// Split fp32 -> tf32 hi + tf32 lo (vectorized by 4)
// ============================================================================
__global__ void __launch_bounds__(256) splitk(const float* __restrict__ s,
        unsigned* __restrict__ hi, unsigned* __restrict__ lo, int n4)
{
    int i = blockIdx.x * 256 + threadIdx.x;
    if (i >= n4) return;
    float4 x = ((const float4*)s)[i];
    uint4 h, l;
    h.x = f2t(x.x); l.x = f2t(x.x - __uint_as_float(h.x));
    h.y = f2t(x.y); l.y = f2t(x.y - __uint_as_float(h.y));
    h.z = f2t(x.z); l.z = f2t(x.z - __uint_as_float(h.z));
    h.w = f2t(x.w); l.w = f2t(x.w - __uint_as_float(h.w));
    ((uint4*)hi)[i] = h;
    ((uint4*)lo)[i] = l;
}

// ============================================================================
// Pipelined split-tf32 GEMM. C[M,3072] = A @ W + bias (A,W pre-split hi/lo).
// BM=BN=128, BK=32, 2-stage cp.async double buffer. 256 threads = 8 warps
// (4m x 2n), warp tile 32x64, m16n8k8, 3 MMA per logical MMA (hh, hl, lh).
// Row-range dual weights: rows < 512 use set A (txt stream), else set B.
// blockIdx.z selects one of up to 3 weight sets (q/k/v fusion).
// ============================================================================
struct DualW {
    const unsigned *Bh_a, *Bl_a; const float* bias_a; float* C_a;
    const unsigned *Bh_b, *Bl_b; const float* bias_b; float* C_b;
};
struct GemmArgs {
    const unsigned *Ah, *Al;
    DualW w[3];
};

#define SA_STRIDE 36
#define SB_STRIDE 132
#define SA_TILE (128 * SA_STRIDE)   // u32 per stage
#define SB_TILE (32 * SB_STRIDE)
#define GEMM_SMEM ((2 * SA_TILE * 2 + 2 * SB_TILE * 2) * 4)

__global__ void __launch_bounds__(256) gemm_split(GemmArgs ga)
{
    extern __shared__ unsigned smg[];
    unsigned* sAh = smg;
    unsigned* sAl = sAh + 2 * SA_TILE;
    unsigned* sBh = sAl + 2 * SA_TILE;
    unsigned* sBl = sBh + 2 * SB_TILE;

    const DualW& w = ga.w[blockIdx.z];
    const int mBase = blockIdx.y * 128;
    const int nBase = blockIdx.x * 128;
    const bool low = (mBase < TXT_N);
    const unsigned* __restrict__ Bh = low ? w.Bh_a : w.Bh_b;
    const unsigned* __restrict__ Bl = low ? w.Bl_a : w.Bl_b;
    const float* __restrict__ bias = low ? w.bias_a : w.bias_b;
    float* __restrict__ C = low ? (w.C_a + (size_t)mBase * DIMW)
                                : (w.C_b + (size_t)(mBase - TXT_N) * DIMW);
    const unsigned* __restrict__ Ah = ga.Ah;
    const unsigned* __restrict__ Al = ga.Al;

    const int tid  = threadIdx.x;
    const int lane = tid & 31;
    const int warp = tid >> 5;
    const int wm = warp >> 1;
    const int wn = warp & 1;

    // ---- stage loader ----
    auto load_stage = [&](int kb, int buf) {
        unsigned* dAh = sAh + buf * SA_TILE;
        unsigned* dAl = sAl + buf * SA_TILE;
        unsigned* dBh = sBh + buf * SB_TILE;
        unsigned* dBl = sBl + buf * SB_TILE;
        #pragma unroll
        for (int i = 0; i < 4; i++) {
            int c = tid + i * 256;
            int row = c >> 3, col = (c & 7) * 4;
            size_t g = (size_t)(mBase + row) * DIMW + kb * 32 + col;
            unsigned sa = (unsigned)__cvta_generic_to_shared(dAh + row * SA_STRIDE + col);
            cpa16(sa, Ah + g);
            unsigned sa2 = (unsigned)__cvta_generic_to_shared(dAl + row * SA_STRIDE + col);
            cpa16(sa2, Al + g);
        }
        #pragma unroll
        for (int i = 0; i < 4; i++) {
            int c = tid + i * 256;
            int row = c >> 5, col = (c & 31) * 4;
            size_t g = (size_t)(kb * 32 + row) * DIMW + nBase + col;
            unsigned sb = (unsigned)__cvta_generic_to_shared(dBh + row * SB_STRIDE + col);
            cpa16(sb, Bh + g);
            unsigned sb2 = (unsigned)__cvta_generic_to_shared(dBl + row * SB_STRIDE + col);
            cpa16(sb2, Bl + g);
        }
        cpa_commit();
    };

    float acc[2][8][4];
    #pragma unroll
    for (int i = 0; i < 2; i++)
        #pragma unroll
        for (int j = 0; j < 8; j++)
            #pragma unroll
            for (int p = 0; p < 4; p++) acc[i][j][p] = 0.f;

    const int NK = DIMW / 32;   // 96
    load_stage(0, 0);

    for (int kb = 0; kb < NK; kb++) {
        if (kb + 1 < NK) {
            load_stage(kb + 1, (kb + 1) & 1);
            asm volatile("cp.async.wait_group 1;\n");
        } else {
            asm volatile("cp.async.wait_group 0;\n");
        }
        __syncthreads();

        const unsigned* cAh = sAh + (kb & 1) * SA_TILE;
        const unsigned* cAl = sAl + (kb & 1) * SA_TILE;
        const unsigned* cBh = sBh + (kb & 1) * SB_TILE;
        const unsigned* cBl = sBl + (kb & 1) * SB_TILE;

        #pragma unroll
        for (int ks = 0; ks < 4; ks++) {
            const int kc = ks * 8 + (lane & 3);
            unsigned ah[2][4], al[2][4];
            #pragma unroll
            for (int mt = 0; mt < 2; mt++) {
                int r = wm * 32 + mt * 16 + (lane >> 2);
                ah[mt][0] = cAh[r * SA_STRIDE + kc];
                ah[mt][1] = cAh[(r + 8) * SA_STRIDE + kc];
                ah[mt][2] = cAh[r * SA_STRIDE + kc + 4];
                ah[mt][3] = cAh[(r + 8) * SA_STRIDE + kc + 4];
                al[mt][0] = cAl[r * SA_STRIDE + kc];
                al[mt][1] = cAl[(r + 8) * SA_STRIDE + kc];
                al[mt][2] = cAl[r * SA_STRIDE + kc + 4];
                al[mt][3] = cAl[(r + 8) * SA_STRIDE + kc + 4];
            }
            #pragma unroll
            for (int nt = 0; nt < 8; nt++) {
                int cn = wn * 64 + nt * 8 + (lane >> 2);
                unsigned bh0 = cBh[(ks * 8 + (lane & 3)) * SB_STRIDE + cn];
                unsigned bh1 = cBh[(ks * 8 + (lane & 3) + 4) * SB_STRIDE + cn];
                unsigned bl0 = cBl[(ks * 8 + (lane & 3)) * SB_STRIDE + cn];
                unsigned bl1 = cBl[(ks * 8 + (lane & 3) + 4) * SB_STRIDE + cn];
                #pragma unroll
                for (int mt = 0; mt < 2; mt++) {
                    mma8(acc[mt][nt], ah[mt][0], ah[mt][1], ah[mt][2], ah[mt][3], bh0, bh1);
                    mma8(acc[mt][nt], ah[mt][0], ah[mt][1], ah[mt][2], ah[mt][3], bl0, bl1);
                    mma8(acc[mt][nt], al[mt][0], al[mt][1], al[mt][2], al[mt][3], bh0, bh1);
                }
            }
        }
        __syncthreads();
    }

    // epilogue
    #pragma unroll
    for (int mt = 0; mt < 2; mt++) {
        int r = wm * 32 + mt * 16 + (lane >> 2);
        #pragma unroll
        for (int nt = 0; nt < 8; nt++) {
            int cgl = nBase + wn * 64 + nt * 8 + (lane & 3) * 2;
            float b0 = bias[cgl], b1 = bias[cgl + 1];
            C[(size_t)r * DIMW + cgl]           = acc[mt][nt][0] + b0;
            C[(size_t)r * DIMW + cgl + 1]       = acc[mt][nt][1] + b1;
            C[(size_t)(r + 8) * DIMW + cgl]     = acc[mt][nt][2] + b0;
            C[(size_t)(r + 8) * DIMW + cgl + 1] = acc[mt][nt][3] + b1;
        }
    }
}

// ============================================================================
// Fused per-head RMSNorm + interleaved RoPE, in place on q and k.
// ============================================================================
__global__ void __launch_bounds__(128) norm_rope(float* __restrict__ q, float* __restrict__ k,
        const float* __restrict__ nq, const float* __restrict__ nk,
        const float* __restrict__ naq, const float* __restrict__ nak,
        const float* __restrict__ rc, const float* __restrict__ rs)
{
    const int gw   = blockIdx.x * 4 + (threadIdx.x >> 5);
    const int lane = threadIdx.x & 31;
    const int t = gw / NH, h = gw % NH;
    const size_t base = (size_t)t * DIMW + h * HD + lane * 4;
    const float* wq = (t < TXT_N) ? naq : nq;
    const float* wk = (t < TXT_N) ? nak : nk;
    const float4 c4 = *(const float4*)(rc + (size_t)t * HD + lane * 4);
    const float4 s4 = *(const float4*)(rs + (size_t)t * HD + lane * 4);

    #pragma unroll
    for (int which = 0; which < 2; which++) {
        float* buf = which ? k : q;
        const float* wv = which ? wk : wq;
        float4 x = *(float4*)(buf + base);
        float ss = x.x * x.x + x.y * x.y + x.z * x.z + x.w * x.w;
        ss += __shfl_xor_sync(0xffffffffu, ss, 16);
        ss += __shfl_xor_sync(0xffffffffu, ss, 8);
        ss += __shfl_xor_sync(0xffffffffu, ss, 4);
        ss += __shfl_xor_sync(0xffffffffu, ss, 2);
        ss += __shfl_xor_sync(0xffffffffu, ss, 1);
        float r = rsqrtf(ss * (1.0f / HD) + 1e-6f);
        float4 w4 = *(const float4*)(wv + lane * 4);
        x.x *= r * w4.x; x.y *= r * w4.y; x.z *= r * w4.z; x.w *= r * w4.w;
        float4 y;
        y.x = x.x * c4.x - x.y * s4.x;
        y.y = x.y * c4.y + x.x * s4.y;
        y.z = x.z * c4.z - x.w * s4.z;
        y.w = x.w * c4.w + x.z * s4.w;
        *(float4*)(buf + base) = y;
    }
}

// ============================================================================
// Flash attention (unchanged from R1 passing version).
// ============================================================================
__global__ void __launch_bounds__(128) flash(const float* __restrict__ q,
        const float* __restrict__ k, const float* __restrict__ v, float* __restrict__ o)
{
    extern __shared__ unsigned sm[];
    unsigned* Qh = sm;
    unsigned* Ql = Qh + 64 * 132;
    unsigned* Kh = Ql + 64 * 132;
    unsigned* Kl = Kh + 64 * 132;
    unsigned* Vs = Kl + 64 * 132;
    unsigned* Ps = Vs + 64 * 132;   // 64 x 68

    const int tid = threadIdx.x, lane = tid & 31, w = tid >> 5;
    const int qt = blockIdx.x, h = blockIdx.y;
    const int qb = qt * 64;
    const bool isref = (qb >= TXT_N) && (qb < TXT_N + REF_N);
    const int kv0 = isref ? TXT_N : 0;
    const int nkt = isref ? (REF_N / 64) : (STOT_N / 64);

    #pragma unroll
    for (int i = 0; i < 16; i++) {
        int f = tid + i * 128;
        int row = f >> 5, d4 = f & 31;
        float4 x = *(const float4*)(q + (size_t)(qb + row) * DIMW + h * HD + d4 * 4);
        float vv[4] = {x.x, x.y, x.z, x.w};
        #pragma unroll
        for (int j = 0; j < 4; j++) {
            unsigned hh = f2t(vv[j]);
            Qh[row * 132 + d4 * 4 + j] = hh;
            Ql[row * 132 + d4 * 4 + j] = f2t(vv[j] - __uint_as_float(hh));
        }
    }

    float O[16][4];
    #pragma unroll
    for (int i = 0; i < 16; i++)
        #pragma unroll
        for (int j = 0; j < 4; j++) O[i][j] = 0.f;
    float m0 = -1e30f, m1 = -1e30f, l0 = 0.f, l1 = 0.f;
    const int r0 = w * 16 + (lane >> 2);

    for (int it = 0; it < nkt; it++) {
        __syncthreads();
        const int kt0 = kv0 + it * 64;
        #pragma unroll
        for (int i = 0; i < 16; i++) {
            int f = tid + i * 128;
            int row = f >> 5, d4 = f & 31;
            float4 x = *(const float4*)(k + (size_t)(kt0 + row) * DIMW + h * HD + d4 * 4);
            float vv[4] = {x.x, x.y, x.z, x.w};
            #pragma unroll
            for (int j = 0; j < 4; j++) {
                unsigned hh = f2t(vv[j]);
                Kh[row * 132 + d4 * 4 + j] = hh;
                Kl[row * 132 + d4 * 4 + j] = f2t(vv[j] - __uint_as_float(hh));
            }
            float4 y = *(const float4*)(v + (size_t)(kt0 + row) * DIMW + h * HD + d4 * 4);
            Vs[row * 132 + d4 * 4 + 0] = f2t(y.x);
            Vs[row * 132 + d4 * 4 + 1] = f2t(y.y);
            Vs[row * 132 + d4 * 4 + 2] = f2t(y.z);
            Vs[row * 132 + d4 * 4 + 3] = f2t(y.w);
        }
        __syncthreads();

        float s[8][4];
        #pragma unroll
        for (int i = 0; i < 8; i++)
            #pragma unroll
            for (int j = 0; j < 4; j++) s[i][j] = 0.f;
        #pragma unroll
        for (int ks = 0; ks < 16; ks++) {
            const int kc = ks * 8 + (lane & 3);
            unsigned a0 = Qh[r0 * 132 + kc],     a1 = Qh[(r0 + 8) * 132 + kc];
            unsigned a2 = Qh[r0 * 132 + kc + 4], a3 = Qh[(r0 + 8) * 132 + kc + 4];
            unsigned e0 = Ql[r0 * 132 + kc],     e1 = Ql[(r0 + 8) * 132 + kc];
            unsigned e2 = Ql[r0 * 132 + kc + 4], e3 = Ql[(r0 + 8) * 132 + kc + 4];
            #pragma unroll
            for (int nt = 0; nt < 8; nt++) {
                int bn = nt * 8 + (lane >> 2);
                unsigned bh0 = Kh[bn * 132 + kc], bh1 = Kh[bn * 132 + kc + 4];
                unsigned bl0 = Kl[bn * 132 + kc], bl1 = Kl[bn * 132 + kc + 4];
                mma8(s[nt], a0, a1, a2, a3, bh0, bh1);
                mma8(s[nt], a0, a1, a2, a3, bl0, bl1);
                mma8(s[nt], e0, e1, e2, e3, bh0, bh1);
            }
        }
        const float sc = 0.08838834764831845f;
        float rm0 = -1e30f, rm1 = -1e30f;
        #pragma unroll
        for (int nt = 0; nt < 8; nt++) {
            s[nt][0] *= sc; s[nt][1] *= sc; s[nt][2] *= sc; s[nt][3] *= sc;
            rm0 = fmaxf(rm0, fmaxf(s[nt][0], s[nt][1]));
            rm1 = fmaxf(rm1, fmaxf(s[nt][2], s[nt][3]));
        }
        rm0 = fmaxf(rm0, __shfl_xor_sync(0xffffffffu, rm0, 1));
        rm0 = fmaxf(rm0, __shfl_xor_sync(0xffffffffu, rm0, 2));
        rm1 = fmaxf(rm1, __shfl_xor_sync(0xffffffffu, rm1, 1));
        rm1 = fmaxf(rm1, __shfl_xor_sync(0xffffffffu, rm1, 2));
        float mn0 = fmaxf(m0, rm0), mn1 = fmaxf(m1, rm1);
        float al0 = __expf(m0 - mn0), al1 = __expf(m1 - mn1);
        float rs0 = 0.f, rs1 = 0.f;
        #pragma unroll
        for (int nt = 0; nt < 8; nt++) {
            s[nt][0] = __expf(s[nt][0] - mn0); s[nt][1] = __expf(s[nt][1] - mn0);
            s[nt][2] = __expf(s[nt][2] - mn1); s[nt][3] = __expf(s[nt][3] - mn1);
            rs0 += s[nt][0] + s[nt][1];
            rs1 += s[nt][2] + s[nt][3];
        }
        rs0 += __shfl_xor_sync(0xffffffffu, rs0, 1);
        rs0 += __shfl_xor_sync(0xffffffffu, rs0, 2);
        rs1 += __shfl_xor_sync(0xffffffffu, rs1, 1);
        rs1 += __shfl_xor_sync(0xffffffffu, rs1, 2);
        l0 = l0 * al0 + rs0; l1 = l1 * al1 + rs1;
        m0 = mn0; m1 = mn1;
        #pragma unroll
        for (int nt = 0; nt < 16; nt++) {
            O[nt][0] *= al0; O[nt][1] *= al0; O[nt][2] *= al1; O[nt][3] *= al1;
        }
        #pragma unroll
        for (int nt = 0; nt < 8; nt++) {
            int pc = nt * 8 + (lane & 3) * 2;
            Ps[r0 * 68 + pc]           = f2t(s[nt][0]);
            Ps[r0 * 68 + pc + 1]       = f2t(s[nt][1]);
            Ps[(r0 + 8) * 68 + pc]     = f2t(s[nt][2]);
            Ps[(r0 + 8) * 68 + pc + 1] = f2t(s[nt][3]);
        }
        __syncwarp();
        #pragma unroll
        for (int ks = 0; ks < 8; ks++) {
            const int pc = ks * 8 + (lane & 3);
            unsigned p0 = Ps[r0 * 68 + pc],     p1 = Ps[(r0 + 8) * 68 + pc];
            unsigned p2 = Ps[r0 * 68 + pc + 4], p3 = Ps[(r0 + 8) * 68 + pc + 4];
            #pragma unroll
            for (int nt = 0; nt < 16; nt++) {
                int vn = nt * 8 + (lane >> 2);
                unsigned vb0 = Vs[(ks * 8 + (lane & 3)) * 132 + vn];
                unsigned vb1 = Vs[(ks * 8 + (lane & 3) + 4) * 132 + vn];
                mma8(O[nt], p0, p1, p2, p3, vb0, vb1);
            }
        }
    }
    const float i0 = 1.f / l0, i1 = 1.f / l1;
    const int tok0 = qb + r0;
    #pragma unroll
    for (int nt = 0; nt < 16; nt++) {
        int col = h * HD + nt * 8 + (lane & 3) * 2;
        o[(size_t)tok0 * DIMW + col]           = O[nt][0] * i0;
        o[(size_t)tok0 * DIMW + col + 1]       = O[nt][1] * i0;
        o[(size_t)(tok0 + 8) * DIMW + col]     = O[nt][2] * i1;
        o[(size_t)(tok0 + 8) * DIMW + col + 1] = O[nt][3] * i1;
    }
}

static const int FLASH_SMEM = (5 * 64 * 132 + 64 * 68) * 4;  // 186368 B

extern "C" void kernel_launch(void* const* d_in, const int* in_sizes, int n_in,
                              void* d_out, int out_size) {
    const float* hs  = (const float*)d_in[0];
    const float* enc = (const float*)d_in[1];
    const float* rc  = (const float*)d_in[2];
    const float* rs  = (const float*)d_in[3];
    const float* wq  = (const float*)d_in[4];
    const float* bq  = (const float*)d_in[5];
    const float* wk  = (const float*)d_in[6];
    const float* bk  = (const float*)d_in[7];
    const float* wv  = (const float*)d_in[8];
    const float* bv  = (const float*)d_in[9];
    const float* waq = (const float*)d_in[10];
    const float* baq = (const float*)d_in[11];
    const float* wak = (const float*)d_in[12];
    const float* bak = (const float*)d_in[13];
    const float* wav = (const float*)d_in[14];
    const float* bav = (const float*)d_in[15];
    const float* nq  = (const float*)d_in[16];
    const float* nk  = (const float*)d_in[17];
    const float* naq = (const float*)d_in[18];
    const float* nak = (const float*)d_in[19];
    const float* wo  = (const float*)d_in[20];
    const float* bo  = (const float*)d_in[21];
    const float* wao = (const float*)d_in[22];
    const float* bao = (const float*)d_in[23];
    float* out = (float*)d_out;

    float *qp, *kp, *vp, *op;
    unsigned *ahp, *alp, *whp, *wlp;
    cudaGetSymbolAddress((void**)&qp, g_q);
    cudaGetSymbolAddress((void**)&kp, g_k);
    cudaGetSymbolAddress((void**)&vp, g_v);
    cudaGetSymbolAddress((void**)&op, g_o);
    cudaGetSymbolAddress((void**)&ahp, g_ah);
    cudaGetSymbolAddress((void**)&alp, g_al);
    cudaGetSymbolAddress((void**)&whp, g_wh);
    cudaGetSymbolAddress((void**)&wlp, g_wl);

    cudaFuncSetAttribute(flash, cudaFuncAttributeMaxDynamicSharedMemorySize, FLASH_SMEM);
    cudaFuncSetAttribute(gemm_split, cudaFuncAttributeMaxDynamicSharedMemorySize, GEMM_SMEM);

    // ---- pre-split activations: rows [0,512)=enc, [512,2560)=hs ----
    splitk<<<(TXT_N * DIMW / 4 + 255) / 256, 256>>>(enc, ahp, alp, TXT_N * DIMW / 4);
    splitk<<<(SHID_N * DIMW / 4 + 255) / 256, 256>>>(hs, ahp + (size_t)TXT_N * DIMW,
                                                     alp + (size_t)TXT_N * DIMW, SHID_N * DIMW / 4);
    // ---- pre-split 8 weights: order wq wk wv waq wak wav wo wao ----
    const float* ws[8] = {wq, wk, wv, waq, wak, wav, wo, wao};
    for (int i = 0; i < 8; i++)
        splitk<<<WELTS / 4 / 256, 256>>>(ws[i], whp + (size_t)i * WELTS,
                                         wlp + (size_t)i * WELTS, WELTS / 4);

    // ---- fused QKV projection: grid (24, 20, 3) ----
    {
        GemmArgs ga;
        ga.Ah = ahp; ga.Al = alp;
        float* dst[3] = {qp, kp, vp};
        const float* ba[3] = {baq, bak, bav};
        const float* bb[3] = {bq, bk, bv};
        for (int z = 0; z < 3; z++) {
            ga.w[z].Bh_a = whp + (size_t)(3 + z) * WELTS;  // added (txt) weights
            ga.w[z].Bl_a = wlp + (size_t)(3 + z) * WELTS;
            ga.w[z].bias_a = ba[z];
            ga.w[z].C_a = dst[z];
            ga.w[z].Bh_b = whp + (size_t)z * WELTS;        // hs weights
            ga.w[z].Bl_b = wlp + (size_t)z * WELTS;
            ga.w[z].bias_b = bb[z];
            ga.w[z].C_b = dst[z] + (size_t)TXT_N * DIMW;
        }
        gemm_split<<<dim3(24, 20, 3), 256, GEMM_SMEM>>>(ga);
    }

    norm_rope<<<STOT_N * NH / 4, 128>>>(qp, kp, nq, nk, naq, nak, rc, rs);

    flash<<<dim3(STOT_N / 64, NH), 128, FLASH_SMEM>>>(qp, kp, vp, op);

    // ---- split attention output, then fused out projection ----
    splitk<<<STOT_N * DIMW / 4 / 256, 256>>>(op, ahp, alp, STOT_N * DIMW / 4);
    {
        GemmArgs ga;
        ga.Ah = ahp; ga.Al = alp;
        ga.w[0].Bh_a = whp + 7ull * WELTS;   // wao for txt rows
        ga.w[0].Bl_a = wlp + 7ull * WELTS;
        ga.w[0].bias_a = bao;
        ga.w[0].C_a = out + (size_t)SHID_N * DIMW;
        ga.w[0].Bh_b = whp + 6ull * WELTS;   // wo for hs rows
        ga.w[0].Bl_b = wlp + 6ull * WELTS;
        ga.w[0].bias_b = bo;
        ga.w[0].C_b = out;
        ga.w[1] = ga.w[0]; ga.w[2] = ga.w[0];
        gemm_split<<<dim3(24, 20, 1), 256, GEMM_SMEM>>>(ga);
    }
}

// round 4
// speedup vs baseline: 2.3535x; 1.5675x over previous
#include <cuda_runtime.h>
#include <cuda_bf16.h>
#include <math.h>

#define DIMW 3072
#define NH 24
#define HD 128
#define TXT_N 512
#define REF_N 512
#define STOT_N 2560
#define SHID_N 2048
#define WELTS (DIMW * DIMW)

// ---- scratch (device globals; no allocations allowed) ----
__device__ float g_q[STOT_N * DIMW];
__device__ float g_k[STOT_N * DIMW];
__device__ float g_v[STOT_N * DIMW];
__device__ float g_o[STOT_N * DIMW];
// packed bf16 hi/lo planes (2 bf16 per u32)
__device__ unsigned g_ah[STOT_N * DIMW / 2];
__device__ unsigned g_al[STOT_N * DIMW / 2];
__device__ unsigned g_wh[8ull * WELTS / 2];
__device__ unsigned g_wl[8ull * WELTS / 2];

// ---- helpers ----
__device__ __forceinline__ unsigned f2t(float f) {
    unsigned u; asm("cvt.rna.tf32.f32 %0, %1;" : "=r"(u) : "f"(f)); return u;
}
// pack two floats to bf16x2, a -> low half
__device__ __forceinline__ unsigned pk(float a, float b) {
    unsigned r; asm("cvt.rn.bf16x2.f32 %0, %1, %2;" : "=r"(r) : "f"(b), "f"(a)); return r;
}
__device__ __forceinline__ float hfv(float f) {
    return __bfloat162float(__float2bfloat16_rn(f));
}

__device__ __forceinline__ void mma8(float* c, unsigned a0, unsigned a1, unsigned a2, unsigned a3,
                                     unsigned b0, unsigned b1) {
    asm volatile("mma.sync.aligned.m16n8k8.row.col.f32.tf32.tf32.f32 "
        "{%0,%1,%2,%3}, {%4,%5,%6,%7}, {%8,%9}, {%0,%1,%2,%3};\n"
        : "+f"(c[0]), "+f"(c[1]), "+f"(c[2]), "+f"(c[3])
        : "r"(a0), "r"(a1), "r"(a2), "r"(a3), "r"(b0), "r"(b1));
}
__device__ __forceinline__ void mmab(float* c, const unsigned* a, unsigned b0, unsigned b1) {
    asm volatile("mma.sync.aligned.m16n8k16.row.col.f32.bf16.bf16.f32 "
        "{%0,%1,%2,%3}, {%4,%5,%6,%7}, {%8,%9}, {%0,%1,%2,%3};\n"
        : "+f"(c[0]), "+f"(c[1]), "+f"(c[2]), "+f"(c[3])
        : "r"(a[0]), "r"(a[1]), "r"(a[2]), "r"(a[3]), "r"(b0), "r"(b1));
}
__device__ __forceinline__ void cpa16(unsigned saddr, const void* g) {
    asm volatile("cp.async.ca.shared.global [%0], [%1], 16;\n" :: "r"(saddr), "l"(g));
}
#define LDSM4(r0,r1,r2,r3,addr) \
    asm volatile("ldmatrix.sync.aligned.m8n8.x4.shared.b16 {%0,%1,%2,%3},[%4];" \
        : "=r"(r0),"=r"(r1),"=r"(r2),"=r"(r3) : "r"(addr))
#define LDSM4T(r0,r1,r2,r3,addr) \
    asm volatile("ldmatrix.sync.aligned.m8n8.x4.trans.shared.b16 {%0,%1,%2,%3},[%4];" \
        : "=r"(r0),"=r"(r1),"=r"(r2),"=r"(r3) : "r"(addr))

// ============================================================================
// Split fp32 -> packed bf16 hi plane + bf16 lo (residual) plane.
// ============================================================================
__global__ void __launch_bounds__(256) splitb(const float* __restrict__ s,
        unsigned* __restrict__ hi, unsigned* __restrict__ lo, int n4)
{
    int i = blockIdx.x * 256 + threadIdx.x;
    if (i >= n4) return;
    float4 x = ((const float4*)s)[i];
    float h0 = hfv(x.x), h1 = hfv(x.y), h2 = hfv(x.z), h3 = hfv(x.w);
    uint2 H, L;
    H.x = pk(h0, h1);
    H.y = pk(h2, h3);
    L.x = pk(x.x - h0, x.y - h1);
    L.y = pk(x.z - h2, x.w - h3);
    ((uint2*)hi)[i] = H;
    ((uint2*)lo)[i] = L;
}

// ============================================================================
// bf16-split GEMM: C[M,3072] = A @ W + bias. 3 MMA terms (hh, hl, lh).
// BM=256, BN=128, BK=32, 3-stage cp.async, 512 threads = 16 warps (8m x 2n),
// warp tile 32x64, m16n8k16, ldmatrix fragments.
// ============================================================================
struct DualW {
    const unsigned *Bh_a, *Bl_a; const float* bias_a; float* C_a;
    const unsigned *Bh_b, *Bl_b; const float* bias_b; float* C_b;
};
struct GemmArgs {
    const unsigned *Ah, *Al;
    DualW w[3];
};

#define BM 256
#define BN 128
#define SAW 20                    // A row stride, u32 (40 bf16 = 80B)
#define SBW 68                    // B row stride, u32 (136 bf16 = 272B)
#define SA_T (BM * SAW)           // 5120 u32 per plane per stage
#define SB_T (32 * SBW)           // 2176 u32 per plane per stage
#define STG4 ((2 * SA_T + 2 * SB_T) * 4)   // stage bytes = 58368
#define GEMM_SMEM (3 * STG4)               // 175104 B

__global__ void __launch_bounds__(512) gemm_bf16(GemmArgs ga)
{
    extern __shared__ unsigned smg[];

    const DualW& w = ga.w[blockIdx.z];
    const int mBase = blockIdx.y * BM;
    const int nBase = blockIdx.x * BN;
    const bool low = (mBase < TXT_N);
    const unsigned* __restrict__ Bh = low ? w.Bh_a : w.Bh_b;
    const unsigned* __restrict__ Bl = low ? w.Bl_a : w.Bl_b;
    const float* __restrict__ bias = low ? w.bias_a : w.bias_b;
    float* __restrict__ C = low ? (w.C_a + (size_t)mBase * DIMW)
                                : (w.C_b + (size_t)(mBase - TXT_N) * DIMW);
    const unsigned* __restrict__ Ah = ga.Ah;
    const unsigned* __restrict__ Al = ga.Al;

    const int tid  = threadIdx.x;
    const int lane = tid & 31;
    const int warp = tid >> 5;
    const int wm = warp >> 1;     // 0..7
    const int wn = warp & 1;      // 0..1

    const unsigned smBase = (unsigned)__cvta_generic_to_shared(smg);
    // ldmatrix per-lane byte offsets
    const int quad = lane >> 3;
    const unsigned offA = (unsigned)((wm * 32 + (lane & 7) + (quad & 1) * 8) * 80 + (quad >> 1) * 16);
    const unsigned offB = (unsigned)(((lane & 7) + (quad & 1) * 8) * 272 + (wn * 64 + (quad >> 1) * 8) * 2);

    // ---- stage loader ----
    auto load_stage = [&](int kb, int buf) {
        unsigned base = smBase + buf * STG4;
        #pragma unroll
        for (int i = 0; i < 2; i++) {
            int c = tid + i * 512;               // 0..1023
            int row = c >> 2, seg = c & 3;
            size_t g = (size_t)(mBase + row) * (DIMW / 2) + kb * 16 + seg * 4;
            unsigned so = base + row * 80 + seg * 16;
            cpa16(so, Ah + g);
            cpa16(so + SA_T * 4, Al + g);
        }
        {
            int row = tid >> 4, seg = tid & 15;  // 32 rows x 16 segs
            size_t g = (size_t)(kb * 32 + row) * (DIMW / 2) + (nBase >> 1) + seg * 4;
            unsigned so = base + 2 * SA_T * 4 + row * 272 + seg * 16;
            cpa16(so, Bh + g);
            cpa16(so + SB_T * 4, Bl + g);
        }
        asm volatile("cp.async.commit_group;\n");
    };

    float acc[2][8][4];
    #pragma unroll
    for (int i = 0; i < 2; i++)
        #pragma unroll
        for (int j = 0; j < 8; j++)
            #pragma unroll
            for (int p = 0; p < 4; p++) acc[i][j][p] = 0.f;

    const int NK = DIMW / 32;   // 96
    load_stage(0, 0);
    load_stage(1, 1);

    int buf = 0;
    for (int kb = 0; kb < NK; kb++) {
        if (kb + 2 < NK) {
            asm volatile("cp.async.wait_group 1;\n");
        } else {
            asm volatile("cp.async.wait_group 0;\n");
        }
        __syncthreads();
        if (kb + 2 < NK) load_stage(kb + 2, (kb + 2) % 3);

        const unsigned stb = smBase + buf * STG4;
        const unsigned aHi = stb + offA;
        const unsigned aLo = aHi + SA_T * 4;
        const unsigned bHi = stb + 2 * SA_T * 4 + offB;
        const unsigned bLo = bHi + SB_T * 4;

        #pragma unroll
        for (int k16 = 0; k16 < 2; k16++) {
            unsigned ah[2][4], al[2][4];
            #pragma unroll
            for (int mt = 0; mt < 2; mt++) {
                LDSM4(ah[mt][0], ah[mt][1], ah[mt][2], ah[mt][3], aHi + mt * (16 * 80) + k16 * 32);
                LDSM4(al[mt][0], al[mt][1], al[mt][2], al[mt][3], aLo + mt * (16 * 80) + k16 * 32);
            }
            #pragma unroll
            for (int p = 0; p < 4; p++) {
                unsigned bh[4], bl[4];
                LDSM4T(bh[0], bh[1], bh[2], bh[3], bHi + k16 * (16 * 272) + p * 32);
                LDSM4T(bl[0], bl[1], bl[2], bl[3], bLo + k16 * (16 * 272) + p * 32);
                #pragma unroll
                for (int h = 0; h < 2; h++) {
                    #pragma unroll
                    for (int mt = 0; mt < 2; mt++) {
                        float* c = acc[mt][p * 2 + h];
                        mmab(c, ah[mt], bh[2 * h], bh[2 * h + 1]);
                        mmab(c, ah[mt], bl[2 * h], bl[2 * h + 1]);
                        mmab(c, al[mt], bh[2 * h], bh[2 * h + 1]);
                    }
                }
            }
        }
        buf = (buf + 1) % 3;
    }

    // epilogue
    #pragma unroll
    for (int mt = 0; mt < 2; mt++) {
        int r = wm * 32 + mt * 16 + (lane >> 2);
        #pragma unroll
        for (int nt = 0; nt < 8; nt++) {
            int cg = nBase + wn * 64 + nt * 8 + (lane & 3) * 2;
            float b0 = bias[cg], b1 = bias[cg + 1];
            float2 v0 = make_float2(acc[mt][nt][0] + b0, acc[mt][nt][1] + b1);
            float2 v1 = make_float2(acc[mt][nt][2] + b0, acc[mt][nt][3] + b1);
            *(float2*)&C[(size_t)r * DIMW + cg] = v0;
            *(float2*)&C[(size_t)(r + 8) * DIMW + cg] = v1;
        }
    }
}

// ============================================================================
// Fused per-head RMSNorm + interleaved RoPE, in place on q and k.
// ============================================================================
__global__ void __launch_bounds__(128) norm_rope(float* __restrict__ q, float* __restrict__ k,
        const float* __restrict__ nq, const float* __restrict__ nk,
        const float* __restrict__ naq, const float* __restrict__ nak,
        const float* __restrict__ rc, const float* __restrict__ rs)
{
    const int gw   = blockIdx.x * 4 + (threadIdx.x >> 5);
    const int lane = threadIdx.x & 31;
    const int t = gw / NH, h = gw % NH;
    const size_t base = (size_t)t * DIMW + h * HD + lane * 4;
    const float* wq = (t < TXT_N) ? naq : nq;
    const float* wk = (t < TXT_N) ? nak : nk;
    const float4 c4 = *(const float4*)(rc + (size_t)t * HD + lane * 4);
    const float4 s4 = *(const float4*)(rs + (size_t)t * HD + lane * 4);

    #pragma unroll
    for (int which = 0; which < 2; which++) {
        float* buf = which ? k : q;
        const float* wv = which ? wk : wq;
        float4 x = *(float4*)(buf + base);
        float ss = x.x * x.x + x.y * x.y + x.z * x.z + x.w * x.w;
        ss += __shfl_xor_sync(0xffffffffu, ss, 16);
        ss += __shfl_xor_sync(0xffffffffu, ss, 8);
        ss += __shfl_xor_sync(0xffffffffu, ss, 4);
        ss += __shfl_xor_sync(0xffffffffu, ss, 2);
        ss += __shfl_xor_sync(0xffffffffu, ss, 1);
        float r = rsqrtf(ss * (1.0f / HD) + 1e-6f);
        float4 w4 = *(const float4*)(wv + lane * 4);
        x.x *= r * w4.x; x.y *= r * w4.y; x.z *= r * w4.z; x.w *= r * w4.w;
        float4 y;
        y.x = x.x * c4.x - x.y * s4.x;
        y.y = x.y * c4.y + x.x * s4.y;
        y.z = x.z * c4.z - x.w * s4.z;
        y.w = x.w * c4.w + x.z * s4.w;
        *(float4*)(buf + base) = y;
    }
}

// ============================================================================
// Flash attention (unchanged, known-good).
// ============================================================================
__global__ void __launch_bounds__(128) flash(const float* __restrict__ q,
        const float* __restrict__ k, const float* __restrict__ v, float* __restrict__ o)
{
    extern __shared__ unsigned sm[];
    unsigned* Qh = sm;
    unsigned* Ql = Qh + 64 * 132;
    unsigned* Kh = Ql + 64 * 132;
    unsigned* Kl = Kh + 64 * 132;
    unsigned* Vs = Kl + 64 * 132;
    unsigned* Ps = Vs + 64 * 132;   // 64 x 68

    const int tid = threadIdx.x, lane = tid & 31, w = tid >> 5;
    const int qt = blockIdx.x, h = blockIdx.y;
    const int qb = qt * 64;
    const bool isref = (qb >= TXT_N) && (qb < TXT_N + REF_N);
    const int kv0 = isref ? TXT_N : 0;
    const int nkt = isref ? (REF_N / 64) : (STOT_N / 64);

    #pragma unroll
    for (int i = 0; i < 16; i++) {
        int f = tid + i * 128;
        int row = f >> 5, d4 = f & 31;
        float4 x = *(const float4*)(q + (size_t)(qb + row) * DIMW + h * HD + d4 * 4);
        float vv[4] = {x.x, x.y, x.z, x.w};
        #pragma unroll
        for (int j = 0; j < 4; j++) {
            unsigned hh = f2t(vv[j]);
            Qh[row * 132 + d4 * 4 + j] = hh;
            Ql[row * 132 + d4 * 4 + j] = f2t(vv[j] - __uint_as_float(hh));
        }
    }

    float O[16][4];
    #pragma unroll
    for (int i = 0; i < 16; i++)
        #pragma unroll
        for (int j = 0; j < 4; j++) O[i][j] = 0.f;
    float m0 = -1e30f, m1 = -1e30f, l0 = 0.f, l1 = 0.f;
    const int r0 = w * 16 + (lane >> 2);

    for (int it = 0; it < nkt; it++) {
        __syncthreads();
        const int kt0 = kv0 + it * 64;
        #pragma unroll
        for (int i = 0; i < 16; i++) {
            int f = tid + i * 128;
            int row = f >> 5, d4 = f & 31;
            float4 x = *(const float4*)(k + (size_t)(kt0 + row) * DIMW + h * HD + d4 * 4);
            float vv[4] = {x.x, x.y, x.z, x.w};
            #pragma unroll
            for (int j = 0; j < 4; j++) {
                unsigned hh = f2t(vv[j]);
                Kh[row * 132 + d4 * 4 + j] = hh;
                Kl[row * 132 + d4 * 4 + j] = f2t(vv[j] - __uint_as_float(hh));
            }
            float4 y = *(const float4*)(v + (size_t)(kt0 + row) * DIMW + h * HD + d4 * 4);
            Vs[row * 132 + d4 * 4 + 0] = f2t(y.x);
            Vs[row * 132 + d4 * 4 + 1] = f2t(y.y);
            Vs[row * 132 + d4 * 4 + 2] = f2t(y.z);
            Vs[row * 132 + d4 * 4 + 3] = f2t(y.w);
        }
        __syncthreads();

        float s[8][4];
        #pragma unroll
        for (int i = 0; i < 8; i++)
            #pragma unroll
            for (int j = 0; j < 4; j++) s[i][j] = 0.f;
        #pragma unroll
        for (int ks = 0; ks < 16; ks++) {
            const int kc = ks * 8 + (lane & 3);
            unsigned a0 = Qh[r0 * 132 + kc],     a1 = Qh[(r0 + 8) * 132 + kc];
            unsigned a2 = Qh[r0 * 132 + kc + 4], a3 = Qh[(r0 + 8) * 132 + kc + 4];
            unsigned e0 = Ql[r0 * 132 + kc],     e1 = Ql[(r0 + 8) * 132 + kc];
            unsigned e2 = Ql[r0 * 132 + kc + 4], e3 = Ql[(r0 + 8) * 132 + kc + 4];
            #pragma unroll
            for (int nt = 0; nt < 8; nt++) {
                int bn = nt * 8 + (lane >> 2);
                unsigned bh0 = Kh[bn * 132 + kc], bh1 = Kh[bn * 132 + kc + 4];
                unsigned bl0 = Kl[bn * 132 + kc], bl1 = Kl[bn * 132 + kc + 4];
                mma8(s[nt], a0, a1, a2, a3, bh0, bh1);
                mma8(s[nt], a0, a1, a2, a3, bl0, bl1);
                mma8(s[nt], e0, e1, e2, e3, bh0, bh1);
            }
        }
        const float sc = 0.08838834764831845f;
        float rm0 = -1e30f, rm1 = -1e30f;
        #pragma unroll
        for (int nt = 0; nt < 8; nt++) {
            s[nt][0] *= sc; s[nt][1] *= sc; s[nt][2] *= sc; s[nt][3] *= sc;
            rm0 = fmaxf(rm0, fmaxf(s[nt][0], s[nt][1]));
            rm1 = fmaxf(rm1, fmaxf(s[nt][2], s[nt][3]));
        }
        rm0 = fmaxf(rm0, __shfl_xor_sync(0xffffffffu, rm0, 1));
        rm0 = fmaxf(rm0, __shfl_xor_sync(0xffffffffu, rm0, 2));
        rm1 = fmaxf(rm1, __shfl_xor_sync(0xffffffffu, rm1, 1));
        rm1 = fmaxf(rm1, __shfl_xor_sync(0xffffffffu, rm1, 2));
        float mn0 = fmaxf(m0, rm0), mn1 = fmaxf(m1, rm1);
        float al0 = __expf(m0 - mn0), al1 = __expf(m1 - mn1);
        float rs0 = 0.f, rs1 = 0.f;
        #pragma unroll
        for (int nt = 0; nt < 8; nt++) {
            s[nt][0] = __expf(s[nt][0] - mn0); s[nt][1] = __expf(s[nt][1] - mn0);
            s[nt][2] = __expf(s[nt][2] - mn1); s[nt][3] = __expf(s[nt][3] - mn1);
            rs0 += s[nt][0] + s[nt][1];
            rs1 += s[nt][2] + s[nt][3];
        }
        rs0 += __shfl_xor_sync(0xffffffffu, rs0, 1);
        rs0 += __shfl_xor_sync(0xffffffffu, rs0, 2);
        rs1 += __shfl_xor_sync(0xffffffffu, rs1, 1);
        rs1 += __shfl_xor_sync(0xffffffffu, rs1, 2);
        l0 = l0 * al0 + rs0; l1 = l1 * al1 + rs1;
        m0 = mn0; m1 = mn1;
        #pragma unroll
        for (int nt = 0; nt < 16; nt++) {
            O[nt][0] *= al0; O[nt][1] *= al0; O[nt][2] *= al1; O[nt][3] *= al1;
        }
        #pragma unroll
        for (int nt = 0; nt < 8; nt++) {
            int pc = nt * 8 + (lane & 3) * 2;
            Ps[r0 * 68 + pc]           = f2t(s[nt][0]);
            Ps[r0 * 68 + pc + 1]       = f2t(s[nt][1]);
            Ps[(r0 + 8) * 68 + pc]     = f2t(s[nt][2]);
            Ps[(r0 + 8) * 68 + pc + 1] = f2t(s[nt][3]);
        }
        __syncwarp();
        #pragma unroll
        for (int ks = 0; ks < 8; ks++) {
            const int pc = ks * 8 + (lane & 3);
            unsigned p0 = Ps[r0 * 68 + pc],     p1 = Ps[(r0 + 8) * 68 + pc];
            unsigned p2 = Ps[r0 * 68 + pc + 4], p3 = Ps[(r0 + 8) * 68 + pc + 4];
            #pragma unroll
            for (int nt = 0; nt < 16; nt++) {
                int vn = nt * 8 + (lane >> 2);
                unsigned vb0 = Vs[(ks * 8 + (lane & 3)) * 132 + vn];
                unsigned vb1 = Vs[(ks * 8 + (lane & 3) + 4) * 132 + vn];
                mma8(O[nt], p0, p1, p2, p3, vb0, vb1);
            }
        }
    }
    const float i0 = 1.f / l0, i1 = 1.f / l1;
    const int tok0 = qb + r0;
    #pragma unroll
    for (int nt = 0; nt < 16; nt++) {
        int col = h * HD + nt * 8 + (lane & 3) * 2;
        o[(size_t)tok0 * DIMW + col]           = O[nt][0] * i0;
        o[(size_t)tok0 * DIMW + col + 1]       = O[nt][1] * i0;
        o[(size_t)(tok0 + 8) * DIMW + col]     = O[nt][2] * i1;
        o[(size_t)(tok0 + 8) * DIMW + col + 1] = O[nt][3] * i1;
    }
}

static const int FLASH_SMEM = (5 * 64 * 132 + 64 * 68) * 4;  // 186368 B

extern "C" void kernel_launch(void* const* d_in, const int* in_sizes, int n_in,
                              void* d_out, int out_size) {
    const float* hs  = (const float*)d_in[0];
    const float* enc = (const float*)d_in[1];
    const float* rc  = (const float*)d_in[2];
    const float* rs  = (const float*)d_in[3];
    const float* wq  = (const float*)d_in[4];
    const float* bq  = (const float*)d_in[5];
    const float* wk  = (const float*)d_in[6];
    const float* bk  = (const float*)d_in[7];
    const float* wv  = (const float*)d_in[8];
    const float* bv  = (const float*)d_in[9];
    const float* waq = (const float*)d_in[10];
    const float* baq = (const float*)d_in[11];
    const float* wak = (const float*)d_in[12];
    const float* bak = (const float*)d_in[13];
    const float* wav = (const float*)d_in[14];
    const float* bav = (const float*)d_in[15];
    const float* nq  = (const float*)d_in[16];
    const float* nk  = (const float*)d_in[17];
    const float* naq = (const float*)d_in[18];
    const float* nak = (const float*)d_in[19];
    const float* wo  = (const float*)d_in[20];
    const float* bo  = (const float*)d_in[21];
    const float* wao = (const float*)d_in[22];
    const float* bao = (const float*)d_in[23];
    float* out = (float*)d_out;

    float *qp, *kp, *vp, *op;
    unsigned *ahp, *alp, *whp, *wlp;
    cudaGetSymbolAddress((void**)&qp, g_q);
    cudaGetSymbolAddress((void**)&kp, g_k);
    cudaGetSymbolAddress((void**)&vp, g_v);
    cudaGetSymbolAddress((void**)&op, g_o);
    cudaGetSymbolAddress((void**)&ahp, g_ah);
    cudaGetSymbolAddress((void**)&alp, g_al);
    cudaGetSymbolAddress((void**)&whp, g_wh);
    cudaGetSymbolAddress((void**)&wlp, g_wl);

    cudaFuncSetAttribute(flash, cudaFuncAttributeMaxDynamicSharedMemorySize, FLASH_SMEM);
    cudaFuncSetAttribute(gemm_bf16, cudaFuncAttributeMaxDynamicSharedMemorySize, GEMM_SMEM);

    const size_t WP = (size_t)WELTS / 2;      // u32 per weight plane
    const size_t AROW = DIMW / 2;             // u32 per activation row

    // ---- pre-split activations: rows [0,512)=enc, [512,2560)=hs ----
    splitb<<<TXT_N * DIMW / 4 / 256, 256>>>(enc, ahp, alp, TXT_N * DIMW / 4);
    splitb<<<SHID_N * DIMW / 4 / 256, 256>>>(hs, ahp + TXT_N * AROW, alp + TXT_N * AROW,
                                             SHID_N * DIMW / 4);
    // ---- pre-split 8 weights: order wq wk wv waq wak wav wo wao ----
    const float* ws[8] = {wq, wk, wv, waq, wak, wav, wo, wao};
    for (int i = 0; i < 8; i++)
        splitb<<<WELTS / 4 / 256, 256>>>(ws[i], whp + (size_t)i * WP,
                                         wlp + (size_t)i * WP, WELTS / 4);

    // ---- fused QKV projection: grid (24, 10, 3) ----
    {
        GemmArgs ga;
        ga.Ah = ahp; ga.Al = alp;
        float* dst[3] = {qp, kp, vp};
        const float* ba[3] = {baq, bak, bav};
        const float* bb[3] = {bq, bk, bv};
        for (int z = 0; z < 3; z++) {
            ga.w[z].Bh_a = whp + (size_t)(3 + z) * WP;   // added (txt) weights
            ga.w[z].Bl_a = wlp + (size_t)(3 + z) * WP;
            ga.w[z].bias_a = ba[z];
            ga.w[z].C_a = dst[z];
            ga.w[z].Bh_b = whp + (size_t)z * WP;         // hs weights
            ga.w[z].Bl_b = wlp + (size_t)z * WP;
            ga.w[z].bias_b = bb[z];
            ga.w[z].C_b = dst[z] + (size_t)TXT_N * DIMW;
        }
        gemm_bf16<<<dim3(24, 10, 3), 512, GEMM_SMEM>>>(ga);
    }

    norm_rope<<<STOT_N * NH / 4, 128>>>(qp, kp, nq, nk, naq, nak, rc, rs);

    flash<<<dim3(STOT_N / 64, NH), 128, FLASH_SMEM>>>(qp, kp, vp, op);

    // ---- split attention output, then fused out projection ----
    splitb<<<STOT_N * DIMW / 4 / 256, 256>>>(op, ahp, alp, STOT_N * DIMW / 4);
    {
        GemmArgs ga;
        ga.Ah = ahp; ga.Al = alp;
        ga.w[0].Bh_a = whp + 7ull * WP;   // wao for txt rows
        ga.w[0].Bl_a = wlp + 7ull * WP;
        ga.w[0].bias_a = bao;
        ga.w[0].C_a = out + (size_t)SHID_N * DIMW;
        ga.w[0].Bh_b = whp + 6ull * WP;   // wo for hs rows
        ga.w[0].Bl_b = wlp + 6ull * WP;
        ga.w[0].bias_b = bo;
        ga.w[0].C_b = out;
        ga.w[1] = ga.w[0]; ga.w[2] = ga.w[0];
        gemm_bf16<<<dim3(24, 10, 1), 512, GEMM_SMEM>>>(ga);
    }
}

// round 6
// speedup vs baseline: 2.5122x; 1.0674x over previous
#include <cuda_runtime.h>
#include <cuda_bf16.h>
#include <math.h>

#define DIMW 3072
#define NH 24
#define HD 128
#define TXT_N 512
#define REF_N 512
#define STOT_N 2560
#define SHID_N 2048
#define WELTS (DIMW * DIMW)

// ---- scratch (device globals; no allocations allowed) ----
__device__ float g_q[STOT_N * DIMW];
__device__ float g_k[STOT_N * DIMW];
__device__ float g_v[STOT_N * DIMW];
// packed bf16 hi/lo planes (2 bf16 per u32). Activations K-major [m][k].
__device__ unsigned g_ah[STOT_N * DIMW / 2];
__device__ unsigned g_al[STOT_N * DIMW / 2];
__device__ unsigned g_wh[8ull * WELTS / 2];
__device__ unsigned g_wl[8ull * WELTS / 2];

// ---- helpers ----
__device__ __forceinline__ unsigned f2t(float f) {
    unsigned u; asm("cvt.rna.tf32.f32 %0, %1;" : "=r"(u) : "f"(f)); return u;
}
__device__ __forceinline__ unsigned pk(float a, float b) {   // a -> low half
    unsigned r; asm("cvt.rn.bf16x2.f32 %0, %1, %2;" : "=r"(r) : "f"(b), "f"(a)); return r;
}
__device__ __forceinline__ float hfv(float f) {
    return __bfloat162float(__float2bfloat16_rn(f));
}
__device__ __forceinline__ void mma8(float* c, unsigned a0, unsigned a1, unsigned a2, unsigned a3,
                                     unsigned b0, unsigned b1) {
    asm volatile("mma.sync.aligned.m16n8k8.row.col.f32.tf32.tf32.f32 "
        "{%0,%1,%2,%3}, {%4,%5,%6,%7}, {%8,%9}, {%0,%1,%2,%3};\n"
        : "+f"(c[0]), "+f"(c[1]), "+f"(c[2]), "+f"(c[3])
        : "r"(a0), "r"(a1), "r"(a2), "r"(a3), "r"(b0), "r"(b1));
}
__device__ __forceinline__ void mmab(float* c, const unsigned* a, unsigned b0, unsigned b1) {
    asm volatile("mma.sync.aligned.m16n8k16.row.col.f32.bf16.bf16.f32 "
        "{%0,%1,%2,%3}, {%4,%5,%6,%7}, {%8,%9}, {%0,%1,%2,%3};\n"
        : "+f"(c[0]), "+f"(c[1]), "+f"(c[2]), "+f"(c[3])
        : "r"(a[0]), "r"(a[1]), "r"(a[2]), "r"(a[3]), "r"(b0), "r"(b1));
}
__device__ __forceinline__ void cpa16(unsigned saddr, const void* g) {
    asm volatile("cp.async.ca.shared.global [%0], [%1], 16;\n" :: "r"(saddr), "l"(g));
}
#define LDSM4(r0,r1,r2,r3,addr) \
    asm volatile("ldmatrix.sync.aligned.m8n8.x4.shared.b16 {%0,%1,%2,%3},[%4];" \
        : "=r"(r0),"=r"(r1),"=r"(r2),"=r"(r3) : "r"(addr))
#define LDSM4T(r0,r1,r2,r3,addr) \
    asm volatile("ldmatrix.sync.aligned.m8n8.x4.trans.shared.b16 {%0,%1,%2,%3},[%4];" \
        : "=r"(r0),"=r"(r1),"=r"(r2),"=r"(r3) : "r"(addr))

// ============================================================================
// Split fp32 -> packed bf16 hi + lo planes
// ============================================================================
__global__ void __launch_bounds__(256) splitb(const float* __restrict__ s,
        unsigned* __restrict__ hi, unsigned* __restrict__ lo, int n4)
{
    int i = blockIdx.x * 256 + threadIdx.x;
    if (i >= n4) return;
    float4 x = ((const float4*)s)[i];
    float h0 = hfv(x.x), h1 = hfv(x.y), h2 = hfv(x.z), h3 = hfv(x.w);
    uint2 H, L;
    H.x = pk(h0, h1); H.y = pk(h2, h3);
    L.x = pk(x.x - h0, x.y - h1); L.y = pk(x.z - h2, x.w - h3);
    ((uint2*)hi)[i] = H;
    ((uint2*)lo)[i] = L;
}

// ============================================================================
// Batched weight split (all 8 weights in one launch; z selects weight).
// W[k][n] fp32 kept K-row-major; split into packed planes (no transpose —
// mma.sync GEMM consumes [k][n] layout via LDSM4T, as in R4).
// ============================================================================
struct WSrc { const float* p[8]; };
__global__ void __launch_bounds__(256) wsplit_all(WSrc ws,
        unsigned* __restrict__ hi, unsigned* __restrict__ lo)
{
    const float* __restrict__ W = ws.p[blockIdx.z];
    size_t base = (size_t)blockIdx.z * (WELTS / 2);
    int i = blockIdx.x * 256 + threadIdx.x + blockIdx.y * (256 * 96);
    float4 x = ((const float4*)W)[i];
    float h0 = hfv(x.x), h1 = hfv(x.y), h2 = hfv(x.z), h3 = hfv(x.w);
    uint2 H, L;
    H.x = pk(h0, h1); H.y = pk(h2, h3);
    L.x = pk(x.x - h0, x.y - h1); L.y = pk(x.z - h2, x.w - h3);
    ((uint2*)(hi + base))[i] = H;
    ((uint2*)(lo + base))[i] = L;
}

__global__ void noop() {}

// ============================================================================
// bf16-split GEMM (R4, known-good): C = A @ W + bias, 3 MMA terms.
// BM=256, BN=128, BK=32, 3-stage cp.async, 512 threads.
// ============================================================================
struct DualW {
    const unsigned *Bh_a, *Bl_a; const float* bias_a; float* C_a;
    const unsigned *Bh_b, *Bl_b; const float* bias_b; float* C_b;
};
struct GemmArgs {
    const unsigned *Ah, *Al;
    DualW w[3];
};

#define BM 256
#define BN 128
#define SAW 20
#define SBW 68
#define SA_T (BM * SAW)
#define SB_T (32 * SBW)
#define STG4 ((2 * SA_T + 2 * SB_T) * 4)
#define GEMM_SMEM (3 * STG4)

__global__ void __launch_bounds__(512) gemm_bf16(GemmArgs ga)
{
    extern __shared__ unsigned smg[];

    const DualW& w = ga.w[blockIdx.z];
    const int mBase = blockIdx.y * BM;
    const int nBase = blockIdx.x * BN;
    const bool low = (mBase < TXT_N);
    const unsigned* __restrict__ Bh = low ? w.Bh_a : w.Bh_b;
    const unsigned* __restrict__ Bl = low ? w.Bl_a : w.Bl_b;
    const float* __restrict__ bias = low ? w.bias_a : w.bias_b;
    float* __restrict__ C = low ? (w.C_a + (size_t)mBase * DIMW)
                                : (w.C_b + (size_t)(mBase - TXT_N) * DIMW);
    const unsigned* __restrict__ Ah = ga.Ah;
    const unsigned* __restrict__ Al = ga.Al;

    const int tid  = threadIdx.x;
    const int lane = tid & 31;
    const int warp = tid >> 5;
    const int wm = warp >> 1;
    const int wn = warp & 1;

    const unsigned smBase = (unsigned)__cvta_generic_to_shared(smg);
    const int quad = lane >> 3;
    const unsigned offA = (unsigned)((wm * 32 + (lane & 7) + (quad & 1) * 8) * 80 + (quad >> 1) * 16);
    const unsigned offB = (unsigned)(((lane & 7) + (quad & 1) * 8) * 272 + (wn * 64 + (quad >> 1) * 8) * 2);

    auto load_stage = [&](int kb, int buf) {
        unsigned base = smBase + buf * STG4;
        #pragma unroll
        for (int i = 0; i < 2; i++) {
            int c = tid + i * 512;
            int row = c >> 2, seg = c & 3;
            size_t g = (size_t)(mBase + row) * (DIMW / 2) + kb * 16 + seg * 4;
            unsigned so = base + row * 80 + seg * 16;
            cpa16(so, Ah + g);
            cpa16(so + SA_T * 4, Al + g);
        }
        {
            int row = tid >> 4, seg = tid & 15;
            size_t g = (size_t)(kb * 32 + row) * (DIMW / 2) + (nBase >> 1) + seg * 4;
            unsigned so = base + 2 * SA_T * 4 + row * 272 + seg * 16;
            cpa16(so, Bh + g);
            cpa16(so + SB_T * 4, Bl + g);
        }
        asm volatile("cp.async.commit_group;\n");
    };

    float acc[2][8][4];
    #pragma unroll
    for (int i = 0; i < 2; i++)
        #pragma unroll
        for (int j = 0; j < 8; j++)
            #pragma unroll
            for (int p = 0; p < 4; p++) acc[i][j][p] = 0.f;

    const int NK = DIMW / 32;
    load_stage(0, 0);
    load_stage(1, 1);

    int buf = 0;
    for (int kb = 0; kb < NK; kb++) {
        if (kb + 2 < NK) {
            asm volatile("cp.async.wait_group 1;\n");
        } else {
            asm volatile("cp.async.wait_group 0;\n");
        }
        __syncthreads();
        if (kb + 2 < NK) load_stage(kb + 2, (kb + 2) % 3);

        const unsigned stb = smBase + buf * STG4;
        const unsigned aHi = stb + offA;
        const unsigned aLo = aHi + SA_T * 4;
        const unsigned bHi = stb + 2 * SA_T * 4 + offB;
        const unsigned bLo = bHi + SB_T * 4;

        #pragma unroll
        for (int k16 = 0; k16 < 2; k16++) {
            unsigned ah[2][4], al[2][4];
            #pragma unroll
            for (int mt = 0; mt < 2; mt++) {
                LDSM4(ah[mt][0], ah[mt][1], ah[mt][2], ah[mt][3], aHi + mt * (16 * 80) + k16 * 32);
                LDSM4(al[mt][0], al[mt][1], al[mt][2], al[mt][3], aLo + mt * (16 * 80) + k16 * 32);
            }
            #pragma unroll
            for (int p = 0; p < 4; p++) {
                unsigned bh[4], bl[4];
                LDSM4T(bh[0], bh[1], bh[2], bh[3], bHi + k16 * (16 * 272) + p * 32);
                LDSM4T(bl[0], bl[1], bl[2], bl[3], bLo + k16 * (16 * 272) + p * 32);
                #pragma unroll
                for (int h = 0; h < 2; h++) {
                    #pragma unroll
                    for (int mt = 0; mt < 2; mt++) {
                        float* c = acc[mt][p * 2 + h];
                        mmab(c, ah[mt], bh[2 * h], bh[2 * h + 1]);
                        mmab(c, ah[mt], bl[2 * h], bl[2 * h + 1]);
                        mmab(c, al[mt], bh[2 * h], bh[2 * h + 1]);
                    }
                }
            }
        }
        buf = (buf + 1) % 3;
    }

    #pragma unroll
    for (int mt = 0; mt < 2; mt++) {
        int r = wm * 32 + mt * 16 + (lane >> 2);
        #pragma unroll
        for (int nt = 0; nt < 8; nt++) {
            int cg = nBase + wn * 64 + nt * 8 + (lane & 3) * 2;
            float b0 = bias[cg], b1 = bias[cg + 1];
            float2 v0 = make_float2(acc[mt][nt][0] + b0, acc[mt][nt][1] + b1);
            float2 v1 = make_float2(acc[mt][nt][2] + b0, acc[mt][nt][3] + b1);
            *(float2*)&C[(size_t)r * DIMW + cg] = v0;
            *(float2*)&C[(size_t)(r + 8) * DIMW + cg] = v1;
        }
    }
}

// ============================================================================
// Fused per-head RMSNorm + interleaved RoPE, in place on q and k.
// ============================================================================
__global__ void __launch_bounds__(128) norm_rope(float* __restrict__ q, float* __restrict__ k,
        const float* __restrict__ nq, const float* __restrict__ nk,
        const float* __restrict__ naq, const float* __restrict__ nak,
        const float* __restrict__ rc, const float* __restrict__ rs)
{
    const int gw   = blockIdx.x * 4 + (threadIdx.x >> 5);
    const int lane = threadIdx.x & 31;
    const int t = gw / NH, h = gw % NH;
    const size_t base = (size_t)t * DIMW + h * HD + lane * 4;
    const float* wq = (t < TXT_N) ? naq : nq;
    const float* wk = (t < TXT_N) ? nak : nk;
    const float4 c4 = *(const float4*)(rc + (size_t)t * HD + lane * 4);
    const float4 s4 = *(const float4*)(rs + (size_t)t * HD + lane * 4);

    #pragma unroll
    for (int which = 0; which < 2; which++) {
        float* buf = which ? k : q;
        const float* wv = which ? wk : wq;
        float4 x = *(float4*)(buf + base);
        float ss = x.x * x.x + x.y * x.y + x.z * x.z + x.w * x.w;
        ss += __shfl_xor_sync(0xffffffffu, ss, 16);
        ss += __shfl_xor_sync(0xffffffffu, ss, 8);
        ss += __shfl_xor_sync(0xffffffffu, ss, 4);
        ss += __shfl_xor_sync(0xffffffffu, ss, 2);
        ss += __shfl_xor_sync(0xffffffffu, ss, 1);
        float r = rsqrtf(ss * (1.0f / HD) + 1e-6f);
        float4 w4 = *(const float4*)(wv + lane * 4);
        x.x *= r * w4.x; x.y *= r * w4.y; x.z *= r * w4.z; x.w *= r * w4.w;
        float4 y;
        y.x = x.x * c4.x - x.y * s4.x;
        y.y = x.y * c4.y + x.x * s4.y;
        y.z = x.z * c4.z - x.w * s4.z;
        y.w = x.w * c4.w + x.z * s4.w;
        *(float4*)(buf + base) = y;
    }
}

// ============================================================================
// Flash attention. QK^T: bf16 3-term m16n8k16 (was tf32 k8 — halves MMA count).
// PV: single tf32 m16n8k8 (unchanged; P tf32 rounding dominates rel_err).
// Epilogue writes packed bf16 hi/lo planes directly (fused split for out-proj).
// ============================================================================
__global__ void __launch_bounds__(128) flash(const float* __restrict__ q,
        const float* __restrict__ k, const float* __restrict__ v,
        unsigned* __restrict__ oh, unsigned* __restrict__ ol)
{
    extern __shared__ unsigned sm[];
    unsigned* Qh = sm;                 // 64 x 68 (packed bf16 pairs)
    unsigned* Ql = Qh + 64 * 68;
    unsigned* Kh = Ql + 64 * 68;
    unsigned* Kl = Kh + 64 * 68;
    unsigned* Vs = Kl + 64 * 68;       // 64 x 132 (tf32)
    unsigned* Ps = Vs + 64 * 132;      // 64 x 68 (tf32)

    const int tid = threadIdx.x, lane = tid & 31, w = tid >> 5;
    const int qt = blockIdx.x, h = blockIdx.y;
    const int qb = qt * 64;
    const bool isref = (qb >= TXT_N) && (qb < TXT_N + REF_N);
    const int kv0 = isref ? TXT_N : 0;
    const int nkt = isref ? (REF_N / 64) : (STOT_N / 64);

    // load Q tile 64x128 -> packed bf16 hi/lo
    #pragma unroll
    for (int i = 0; i < 16; i++) {
        int f = tid + i * 128;
        int row = f >> 5, d4 = f & 31;
        float4 x = *(const float4*)(q + (size_t)(qb + row) * DIMW + h * HD + d4 * 4);
        float h0 = hfv(x.x), h1 = hfv(x.y), h2 = hfv(x.z), h3 = hfv(x.w);
        Qh[row * 68 + d4 * 2]     = pk(h0, h1);
        Qh[row * 68 + d4 * 2 + 1] = pk(h2, h3);
        Ql[row * 68 + d4 * 2]     = pk(x.x - h0, x.y - h1);
        Ql[row * 68 + d4 * 2 + 1] = pk(x.z - h2, x.w - h3);
    }

    float O[16][4];
    #pragma unroll
    for (int i = 0; i < 16; i++)
        #pragma unroll
        for (int j = 0; j < 4; j++) O[i][j] = 0.f;
    float m0 = -1e30f, m1 = -1e30f, l0 = 0.f, l1 = 0.f;
    const int r0 = w * 16 + (lane >> 2);

    for (int it = 0; it < nkt; it++) {
        __syncthreads();
        const int kt0 = kv0 + it * 64;
        #pragma unroll
        for (int i = 0; i < 16; i++) {
            int f = tid + i * 128;
            int row = f >> 5, d4 = f & 31;
            float4 x = *(const float4*)(k + (size_t)(kt0 + row) * DIMW + h * HD + d4 * 4);
            float h0 = hfv(x.x), h1 = hfv(x.y), h2 = hfv(x.z), h3 = hfv(x.w);
            Kh[row * 68 + d4 * 2]     = pk(h0, h1);
            Kh[row * 68 + d4 * 2 + 1] = pk(h2, h3);
            Kl[row * 68 + d4 * 2]     = pk(x.x - h0, x.y - h1);
            Kl[row * 68 + d4 * 2 + 1] = pk(x.z - h2, x.w - h3);
            float4 y = *(const float4*)(v + (size_t)(kt0 + row) * DIMW + h * HD + d4 * 4);
            Vs[row * 132 + d4 * 4 + 0] = f2t(y.x);
            Vs[row * 132 + d4 * 4 + 1] = f2t(y.y);
            Vs[row * 132 + d4 * 4 + 2] = f2t(y.z);
            Vs[row * 132 + d4 * 4 + 3] = f2t(y.w);
        }
        __syncthreads();

        // S = Q @ K^T, bf16 3-term (hh + hl + lh), m16n8k16
        float s[8][4];
        #pragma unroll
        for (int i = 0; i < 8; i++)
            #pragma unroll
            for (int j = 0; j < 4; j++) s[i][j] = 0.f;
        #pragma unroll
        for (int ks = 0; ks < 8; ks++) {
            const int kp = ks * 8 + (lane & 3);
            unsigned a[4], e[4];
            a[0] = Qh[r0 * 68 + kp];       a[1] = Qh[(r0 + 8) * 68 + kp];
            a[2] = Qh[r0 * 68 + kp + 4];   a[3] = Qh[(r0 + 8) * 68 + kp + 4];
            e[0] = Ql[r0 * 68 + kp];       e[1] = Ql[(r0 + 8) * 68 + kp];
            e[2] = Ql[r0 * 68 + kp + 4];   e[3] = Ql[(r0 + 8) * 68 + kp + 4];
            #pragma unroll
            for (int nt = 0; nt < 8; nt++) {
                int bn = nt * 8 + (lane >> 2);
                unsigned bh0 = Kh[bn * 68 + kp], bh1 = Kh[bn * 68 + kp + 4];
                unsigned bl0 = Kl[bn * 68 + kp], bl1 = Kl[bn * 68 + kp + 4];
                mmab(s[nt], a, bh0, bh1);
                mmab(s[nt], a, bl0, bl1);
                mmab(s[nt], e, bh0, bh1);
            }
        }
        // online softmax
        const float sc = 0.08838834764831845f;
        float rm0 = -1e30f, rm1 = -1e30f;
        #pragma unroll
        for (int nt = 0; nt < 8; nt++) {
            s[nt][0] *= sc; s[nt][1] *= sc; s[nt][2] *= sc; s[nt][3] *= sc;
            rm0 = fmaxf(rm0, fmaxf(s[nt][0], s[nt][1]));
            rm1 = fmaxf(rm1, fmaxf(s[nt][2], s[nt][3]));
        }
        rm0 = fmaxf(rm0, __shfl_xor_sync(0xffffffffu, rm0, 1));
        rm0 = fmaxf(rm0, __shfl_xor_sync(0xffffffffu, rm0, 2));
        rm1 = fmaxf(rm1, __shfl_xor_sync(0xffffffffu, rm1, 1));
        rm1 = fmaxf(rm1, __shfl_xor_sync(0xffffffffu, rm1, 2));
        float mn0 = fmaxf(m0, rm0), mn1 = fmaxf(m1, rm1);
        float al0 = __expf(m0 - mn0), al1 = __expf(m1 - mn1);
        float rs0 = 0.f, rs1 = 0.f;
        #pragma unroll
        for (int nt = 0; nt < 8; nt++) {
            s[nt][0] = __expf(s[nt][0] - mn0); s[nt][1] = __expf(s[nt][1] - mn0);
            s[nt][2] = __expf(s[nt][2] - mn1); s[nt][3] = __expf(s[nt][3] - mn1);
            rs0 += s[nt][0] + s[nt][1];
            rs1 += s[nt][2] + s[nt][3];
        }
        rs0 += __shfl_xor_sync(0xffffffffu, rs0, 1);
        rs0 += __shfl_xor_sync(0xffffffffu, rs0, 2);
        rs1 += __shfl_xor_sync(0xffffffffu, rs1, 1);
        rs1 += __shfl_xor_sync(0xffffffffu, rs1, 2);
        l0 = l0 * al0 + rs0; l1 = l1 * al1 + rs1;
        m0 = mn0; m1 = mn1;
        #pragma unroll
        for (int nt = 0; nt < 16; nt++) {
            O[nt][0] *= al0; O[nt][1] *= al0; O[nt][2] *= al1; O[nt][3] *= al1;
        }
        // P -> smem (tf32)
        #pragma unroll
        for (int nt = 0; nt < 8; nt++) {
            int pc = nt * 8 + (lane & 3) * 2;
            Ps[r0 * 68 + pc]           = f2t(s[nt][0]);
            Ps[r0 * 68 + pc + 1]       = f2t(s[nt][1]);
            Ps[(r0 + 8) * 68 + pc]     = f2t(s[nt][2]);
            Ps[(r0 + 8) * 68 + pc + 1] = f2t(s[nt][3]);
        }
        __syncwarp();
        // O += P @ V  (tf32 m16n8k8)
        #pragma unroll
        for (int ks = 0; ks < 8; ks++) {
            const int pc = ks * 8 + (lane & 3);
            unsigned p0 = Ps[r0 * 68 + pc],     p1 = Ps[(r0 + 8) * 68 + pc];
            unsigned p2 = Ps[r0 * 68 + pc + 4], p3 = Ps[(r0 + 8) * 68 + pc + 4];
            #pragma unroll
            for (int nt = 0; nt < 16; nt++) {
                int vn = nt * 8 + (lane >> 2);
                unsigned vb0 = Vs[(ks * 8 + (lane & 3)) * 132 + vn];
                unsigned vb1 = Vs[(ks * 8 + (lane & 3) + 4) * 132 + vn];
                mma8(O[nt], p0, p1, p2, p3, vb0, vb1);
            }
        }
    }
    // epilogue: normalize + write packed bf16 hi/lo planes (fused split)
    const float i0 = 1.f / l0, i1 = 1.f / l1;
    const int tok0 = qb + r0;
    #pragma unroll
    for (int nt = 0; nt < 16; nt++) {
        int cp = h * (HD / 2) + nt * 4 + (lane & 3);   // u32 column index
        float a0v = O[nt][0] * i0, b0v = O[nt][1] * i0;
        float ha = hfv(a0v), hb = hfv(b0v);
        oh[(size_t)tok0 * (DIMW / 2) + cp] = pk(ha, hb);
        ol[(size_t)tok0 * (DIMW / 2) + cp] = pk(a0v - ha, b0v - hb);
        float a1v = O[nt][2] * i1, b1v = O[nt][3] * i1;
        ha = hfv(a1v); hb = hfv(b1v);
        oh[(size_t)(tok0 + 8) * (DIMW / 2) + cp] = pk(ha, hb);
        ol[(size_t)(tok0 + 8) * (DIMW / 2) + cp] = pk(a1v - ha, b1v - hb);
    }
}

static const int FLASH_SMEM = (4 * 64 * 68 + 64 * 132 + 64 * 68) * 4;  // 120832 B

extern "C" void kernel_launch(void* const* d_in, const int* in_sizes, int n_in,
                              void* d_out, int out_size) {
    const float* hs  = (const float*)d_in[0];
    const float* enc = (const float*)d_in[1];
    const float* rc  = (const float*)d_in[2];
    const float* rs  = (const float*)d_in[3];
    const float* wq  = (const float*)d_in[4];
    const float* bq  = (const float*)d_in[5];
    const float* wk  = (const float*)d_in[6];
    const float* bk  = (const float*)d_in[7];
    const float* wv  = (const float*)d_in[8];
    const float* bv  = (const float*)d_in[9];
    const float* waq = (const float*)d_in[10];
    const float* baq = (const float*)d_in[11];
    const float* wak = (const float*)d_in[12];
    const float* bak = (const float*)d_in[13];
    const float* wav = (const float*)d_in[14];
    const float* bav = (const float*)d_in[15];
    const float* nq  = (const float*)d_in[16];
    const float* nk  = (const float*)d_in[17];
    const float* naq = (const float*)d_in[18];
    const float* nak = (const float*)d_in[19];
    const float* wo  = (const float*)d_in[20];
    const float* bo  = (const float*)d_in[21];
    const float* wao = (const float*)d_in[22];
    const float* bao = (const float*)d_in[23];
    float* out = (float*)d_out;

    float *qp, *kp, *vp;
    unsigned *ahp, *alp, *whp, *wlp;
    cudaGetSymbolAddress((void**)&qp, g_q);
    cudaGetSymbolAddress((void**)&kp, g_k);
    cudaGetSymbolAddress((void**)&vp, g_v);
    cudaGetSymbolAddress((void**)&ahp, g_ah);
    cudaGetSymbolAddress((void**)&alp, g_al);
    cudaGetSymbolAddress((void**)&whp, g_wh);
    cudaGetSymbolAddress((void**)&wlp, g_wl);

    cudaFuncSetAttribute(flash, cudaFuncAttributeMaxDynamicSharedMemorySize, FLASH_SMEM);
    cudaFuncSetAttribute(gemm_bf16, cudaFuncAttributeMaxDynamicSharedMemorySize, GEMM_SMEM);

    const size_t WP = (size_t)WELTS / 2;
    const size_t AROW = DIMW / 2;

    // 1) weights (one batched launch; order wq wk wv waq wak wav wo wao)
    {
        WSrc ws;
        ws.p[0] = wq; ws.p[1] = wk; ws.p[2] = wv; ws.p[3] = waq;
        ws.p[4] = wak; ws.p[5] = wav; ws.p[6] = wo; ws.p[7] = wao;
        // WELTS/4 = 2359296 float4 per weight; grid (96, 96, 8) * 256 threads
        wsplit_all<<<dim3(96, 96, 8), 256>>>(ws, whp, wlp);
    }
    // 2-3) activations: rows [0,512)=enc, [512,2560)=hs
    splitb<<<TXT_N * DIMW / 4 / 256, 256>>>(enc, ahp, alp, TXT_N * DIMW / 4);
    splitb<<<SHID_N * DIMW / 4 / 256, 256>>>(hs, ahp + TXT_N * AROW, alp + TXT_N * AROW,
                                             SHID_N * DIMW / 4);
    // 4-5) padding so launch #6 (ncu -s 5 -c 1) is the QKV GEMM
    noop<<<1, 32>>>();
    noop<<<1, 32>>>();

    // 6) fused QKV projection
    {
        GemmArgs ga;
        ga.Ah = ahp; ga.Al = alp;
        float* dst[3] = {qp, kp, vp};
        const float* ba[3] = {baq, bak, bav};
        const float* bb[3] = {bq, bk, bv};
        for (int z = 0; z < 3; z++) {
            ga.w[z].Bh_a = whp + (size_t)(3 + z) * WP;
            ga.w[z].Bl_a = wlp + (size_t)(3 + z) * WP;
            ga.w[z].bias_a = ba[z];
            ga.w[z].C_a = dst[z];
            ga.w[z].Bh_b = whp + (size_t)z * WP;
            ga.w[z].Bl_b = wlp + (size_t)z * WP;
            ga.w[z].bias_b = bb[z];
            ga.w[z].C_b = dst[z] + (size_t)TXT_N * DIMW;
        }
        gemm_bf16<<<dim3(24, 10, 3), 512, GEMM_SMEM>>>(ga);
    }

    // 7) norm + rope
    norm_rope<<<STOT_N * NH / 4, 128>>>(qp, kp, nq, nk, naq, nak, rc, rs);

    // 8) flash (writes packed hi/lo planes directly)
    flash<<<dim3(STOT_N / 64, NH), 128, FLASH_SMEM>>>(qp, kp, vp, ahp, alp);

    // 9) fused out projection
    {
        GemmArgs ga;
        ga.Ah = ahp; ga.Al = alp;
        ga.w[0].Bh_a = whp + 7ull * WP;
        ga.w[0].Bl_a = wlp + 7ull * WP;
        ga.w[0].bias_a = bao;
        ga.w[0].C_a = out + (size_t)SHID_N * DIMW;
        ga.w[0].Bh_b = whp + 6ull * WP;
        ga.w[0].Bl_b = wlp + 6ull * WP;
        ga.w[0].bias_b = bo;
        ga.w[0].C_b = out;
        ga.w[1] = ga.w[0]; ga.w[2] = ga.w[0];
        gemm_bf16<<<dim3(24, 10, 1), 512, GEMM_SMEM>>>(ga);
    }
}

// round 10
// speedup vs baseline: 5.2925x; 2.1068x over previous
#include <cuda_runtime.h>
#include <cuda_fp16.h>
#include <math.h>

#define DIMW 3072
#define NH 24
#define HD 128
#define TXT_N 512
#define REF_N 512
#define STOT_N 2560
#define SHID_N 2048
#define WELTS (DIMW * DIMW)

// ---- scratch (device globals; no allocations allowed) ----
__device__ float g_q[STOT_N * DIMW];
__device__ float g_k[STOT_N * DIMW];
__device__ float g_v[STOT_N * DIMW];
// packed fp16 planes (2 fp16 per u32)
__device__ unsigned g_af[STOT_N * DIMW / 2];
__device__ unsigned g_wf[8ull * WELTS / 2];

// ---- helpers ----
__device__ __forceinline__ unsigned pk16(float a, float b) {   // a -> low half
    __half2 h = __floats2half2_rn(a, b);
    return *(unsigned*)&h;
}
__device__ __forceinline__ void mmaf(float* c, const unsigned* a, unsigned b0, unsigned b1) {
    asm volatile("mma.sync.aligned.m16n8k16.row.col.f32.f16.f16.f32 "
        "{%0,%1,%2,%3}, {%4,%5,%6,%7}, {%8,%9}, {%0,%1,%2,%3};\n"
        : "+f"(c[0]), "+f"(c[1]), "+f"(c[2]), "+f"(c[3])
        : "r"(a[0]), "r"(a[1]), "r"(a[2]), "r"(a[3]), "r"(b0), "r"(b1));
}
__device__ __forceinline__ void cpa16(unsigned saddr, const void* g) {
    asm volatile("cp.async.ca.shared.global [%0], [%1], 16;\n" :: "r"(saddr), "l"(g));
}
#define LDSM4(r0,r1,r2,r3,addr) \
    asm volatile("ldmatrix.sync.aligned.m8n8.x4.shared.b16 {%0,%1,%2,%3},[%4];" \
        : "=r"(r0),"=r"(r1),"=r"(r2),"=r"(r3) : "r"(addr))
#define LDSM4T(r0,r1,r2,r3,addr) \
    asm volatile("ldmatrix.sync.aligned.m8n8.x4.trans.shared.b16 {%0,%1,%2,%3},[%4];" \
        : "=r"(r0),"=r"(r1),"=r"(r2),"=r"(r3) : "r"(addr))

// ============================================================================
// fp32 -> packed fp16 plane
// ============================================================================
__global__ void __launch_bounds__(256) convf(const float* __restrict__ s,
        unsigned* __restrict__ d, int n4)
{
    int i = blockIdx.x * 256 + threadIdx.x;
    if (i >= n4) return;
    float4 x = ((const float4*)s)[i];
    uint2 H;
    H.x = pk16(x.x, x.y);
    H.y = pk16(x.z, x.w);
    ((uint2*)d)[i] = H;
}

// batched weight convert: 8 weights, z selects
struct WSrc { const float* p[8]; };
__global__ void __launch_bounds__(256) wconv_all(WSrc ws, unsigned* __restrict__ d)
{
    const float* __restrict__ W = ws.p[blockIdx.z];
    size_t base = (size_t)blockIdx.z * (WELTS / 2);
    int i = blockIdx.x * 256 + threadIdx.x + blockIdx.y * (256 * 96);
    float4 x = ((const float4*)W)[i];
    uint2 H;
    H.x = pk16(x.x, x.y);
    H.y = pk16(x.z, x.w);
    ((uint2*)(d + base))[i] = H;
}

// ============================================================================
// fp16 GEMM: C[M,3072] = A @ W + bias, single MMA term.
// BM=256, BN=128, BK=32, 3-stage cp.async, 512 threads = 16 warps (8m x 2n),
// warp tile 32x64, m16n8k16, ldmatrix fragments.
// Row-range dual weights (txt rows < 512 use set A). blockIdx.z selects op.
// ============================================================================
struct DualW {
    const unsigned* B_a; const float* bias_a; float* C_a;
    const unsigned* B_b; const float* bias_b; float* C_b;
};
struct GemmArgs {
    const unsigned* A;
    DualW w[3];
};

#define BM 256
#define BN 128
#define SA_T (BM * 20)            // u32/stage, A rows 80B (64 data + 16 pad)
#define SB_T (32 * 68)            // u32/stage, B rows 272B (256 data + 16 pad)
#define STG4 ((SA_T + SB_T) * 4)  // 29184 B
#define GEMM_SMEM (3 * STG4)      // 87552 B

__global__ void __launch_bounds__(512) gemm_f16(GemmArgs ga)
{
    extern __shared__ unsigned smg[];

    const DualW& w = ga.w[blockIdx.z];
    const int mBase = blockIdx.y * BM;
    const int nBase = blockIdx.x * BN;
    const bool low = (mBase < TXT_N);
    const unsigned* __restrict__ B = low ? w.B_a : w.B_b;
    const float* __restrict__ bias = low ? w.bias_a : w.bias_b;
    float* __restrict__ C = low ? (w.C_a + (size_t)mBase * DIMW)
                                : (w.C_b + (size_t)(mBase - TXT_N) * DIMW);
    const unsigned* __restrict__ A = ga.A;

    const int tid  = threadIdx.x;
    const int lane = tid & 31;
    const int warp = tid >> 5;
    const int wm = warp >> 1;     // 0..7
    const int wn = warp & 1;      // 0..1

    const unsigned smBase = (unsigned)__cvta_generic_to_shared(smg);
    const int quad = lane >> 3;
    const unsigned offA = (unsigned)((wm * 32 + (lane & 7) + (quad & 1) * 8) * 80 + (quad >> 1) * 16);
    const unsigned offB = (unsigned)(((lane & 7) + (quad & 1) * 8) * 272 + (wn * 64 + (quad >> 1) * 8) * 2);

    auto load_stage = [&](int kb, int buf) {
        unsigned base = smBase + buf * STG4;
        #pragma unroll
        for (int i = 0; i < 2; i++) {
            int c = tid + i * 512;               // 1024 cpa for A
            int row = c >> 2, seg = c & 3;
            size_t g = (size_t)(mBase + row) * (DIMW / 2) + kb * 16 + seg * 4;
            cpa16(base + row * 80 + seg * 16, A + g);
        }
        {
            int row = tid >> 4, seg = tid & 15;  // 512 cpa for B
            size_t g = (size_t)(kb * 32 + row) * (DIMW / 2) + (nBase >> 1) + seg * 4;
            cpa16(base + SA_T * 4 + row * 272 + seg * 16, B + g);
        }
        asm volatile("cp.async.commit_group;\n");
    };

    float acc[2][8][4];
    #pragma unroll
    for (int i = 0; i < 2; i++)
        #pragma unroll
        for (int j = 0; j < 8; j++)
            #pragma unroll
            for (int p = 0; p < 4; p++) acc[i][j][p] = 0.f;

    const int NK = DIMW / 32;   // 96
    load_stage(0, 0);
    load_stage(1, 1);

    int buf = 0;
    for (int kb = 0; kb < NK; kb++) {
        if (kb + 2 < NK) {
            asm volatile("cp.async.wait_group 1;\n");
        } else {
            asm volatile("cp.async.wait_group 0;\n");
        }
        __syncthreads();
        if (kb + 2 < NK) load_stage(kb + 2, (kb + 2) % 3);

        const unsigned stb = smBase + buf * STG4;
        const unsigned aP = stb + offA;
        const unsigned bP = stb + SA_T * 4 + offB;

        #pragma unroll
        for (int k16 = 0; k16 < 2; k16++) {
            unsigned a[2][4];
            #pragma unroll
            for (int mt = 0; mt < 2; mt++)
                LDSM4(a[mt][0], a[mt][1], a[mt][2], a[mt][3], aP + mt * (16 * 80) + k16 * 32);
            #pragma unroll
            for (int p = 0; p < 4; p++) {
                unsigned bh[4];
                LDSM4T(bh[0], bh[1], bh[2], bh[3], bP + k16 * (16 * 272) + p * 32);
                #pragma unroll
                for (int h = 0; h < 2; h++)
                    #pragma unroll
                    for (int mt = 0; mt < 2; mt++)
                        mmaf(acc[mt][p * 2 + h], a[mt], bh[2 * h], bh[2 * h + 1]);
            }
        }
        buf = (buf + 1) % 3;
    }

    #pragma unroll
    for (int mt = 0; mt < 2; mt++) {
        int r = wm * 32 + mt * 16 + (lane >> 2);
        #pragma unroll
        for (int nt = 0; nt < 8; nt++) {
            int cg = nBase + wn * 64 + nt * 8 + (lane & 3) * 2;
            float b0 = bias[cg], b1 = bias[cg + 1];
            float2 v0 = make_float2(acc[mt][nt][0] + b0, acc[mt][nt][1] + b1);
            float2 v1 = make_float2(acc[mt][nt][2] + b0, acc[mt][nt][3] + b1);
            *(float2*)&C[(size_t)r * DIMW + cg] = v0;
            *(float2*)&C[(size_t)(r + 8) * DIMW + cg] = v1;
        }
    }
}

// ============================================================================
// Fused per-head RMSNorm + interleaved RoPE, in place on q and k (fp32).
// ============================================================================
__global__ void __launch_bounds__(128) norm_rope(float* __restrict__ q, float* __restrict__ k,
        const float* __restrict__ nq, const float* __restrict__ nk,
        const float* __restrict__ naq, const float* __restrict__ nak,
        const float* __restrict__ rc, const float* __restrict__ rs)
{
    const int gw   = blockIdx.x * 4 + (threadIdx.x >> 5);
    const int lane = threadIdx.x & 31;
    const int t = gw / NH, h = gw % NH;
    const size_t base = (size_t)t * DIMW + h * HD + lane * 4;
    const float* wq = (t < TXT_N) ? naq : nq;
    const float* wk = (t < TXT_N) ? nak : nk;
    const float4 c4 = *(const float4*)(rc + (size_t)t * HD + lane * 4);
    const float4 s4 = *(const float4*)(rs + (size_t)t * HD + lane * 4);

    #pragma unroll
    for (int which = 0; which < 2; which++) {
        float* buf = which ? k : q;
        const float* wv = which ? wk : wq;
        float4 x = *(float4*)(buf + base);
        float ss = x.x * x.x + x.y * x.y + x.z * x.z + x.w * x.w;
        ss += __shfl_xor_sync(0xffffffffu, ss, 16);
        ss += __shfl_xor_sync(0xffffffffu, ss, 8);
        ss += __shfl_xor_sync(0xffffffffu, ss, 4);
        ss += __shfl_xor_sync(0xffffffffu, ss, 2);
        ss += __shfl_xor_sync(0xffffffffu, ss, 1);
        float r = rsqrtf(ss * (1.0f / HD) + 1e-6f);
        float4 w4 = *(const float4*)(wv + lane * 4);
        x.x *= r * w4.x; x.y *= r * w4.y; x.z *= r * w4.z; x.w *= r * w4.w;
        float4 y;
        y.x = x.x * c4.x - x.y * s4.x;
        y.y = x.y * c4.y + x.x * s4.y;
        y.z = x.z * c4.z - x.w * s4.z;
        y.w = x.w * c4.w + x.z * s4.w;
        *(float4*)(buf + base) = y;
    }
}

// ============================================================================
// Flash attention, all-fp16 MMA (single term). QK: m16n8k16, PV: m16n8k16 with
// V fragments via ldmatrix.trans. Epilogue writes packed fp16 plane (fused
// convert for the out projection).
// FIX vs R7: Q/K row stride is 64 u32 of data (128 fp16) -> stride 68, not 36.
// ============================================================================
#define QS 68
#define KS 68
#define VS 68
#define PS 36
#define V_OFF (64 * QS + 64 * KS)            // u32 offset of V
#define P_OFF (V_OFF + 64 * VS)
#define FLASH_SMEM ((P_OFF + 64 * PS) * 4)   // 61440 B

__global__ void __launch_bounds__(128) flash(const float* __restrict__ q,
        const float* __restrict__ k, const float* __restrict__ v,
        unsigned* __restrict__ of)
{
    extern __shared__ unsigned sm[];
    unsigned* Qs = sm;
    unsigned* Ks = Qs + 64 * QS;
    unsigned* Vs = sm + V_OFF;
    unsigned* Ps = sm + P_OFF;
    const unsigned smBase = (unsigned)__cvta_generic_to_shared(sm);

    const int tid = threadIdx.x, lane = tid & 31, w = tid >> 5;
    const int qt = blockIdx.x, h = blockIdx.y;
    const int qb = qt * 64;
    const bool isref = (qb >= TXT_N) && (qb < TXT_N + REF_N);
    const int kv0 = isref ? TXT_N : 0;
    const int nkt = isref ? (REF_N / 64) : (STOT_N / 64);

    // ldmatrix.trans per-lane offset into V (k-rows x n-cols, 272B rows)
    const int quad = lane >> 3;
    const unsigned offV = (unsigned)(((lane & 7) + (quad & 1) * 8) * (VS * 4) + (quad >> 1) * 16);
    const unsigned vB = smBase + V_OFF * 4 + offV;

    // load Q tile 64x128 -> packed fp16
    #pragma unroll
    for (int i = 0; i < 16; i++) {
        int f = tid + i * 128;
        int row = f >> 5, d4 = f & 31;
        float4 x = *(const float4*)(q + (size_t)(qb + row) * DIMW + h * HD + d4 * 4);
        Qs[row * QS + d4 * 2]     = pk16(x.x, x.y);
        Qs[row * QS + d4 * 2 + 1] = pk16(x.z, x.w);
    }

    float O[16][4];
    #pragma unroll
    for (int i = 0; i < 16; i++)
        #pragma unroll
        for (int j = 0; j < 4; j++) O[i][j] = 0.f;
    float m0 = -1e30f, m1 = -1e30f, l0 = 0.f, l1 = 0.f;
    const int r0 = w * 16 + (lane >> 2);

    for (int it = 0; it < nkt; it++) {
        __syncthreads();
        const int kt0 = kv0 + it * 64;
        #pragma unroll
        for (int i = 0; i < 16; i++) {
            int f = tid + i * 128;
            int row = f >> 5, d4 = f & 31;
            float4 x = *(const float4*)(k + (size_t)(kt0 + row) * DIMW + h * HD + d4 * 4);
            Ks[row * KS + d4 * 2]     = pk16(x.x, x.y);
            Ks[row * KS + d4 * 2 + 1] = pk16(x.z, x.w);
            float4 y = *(const float4*)(v + (size_t)(kt0 + row) * DIMW + h * HD + d4 * 4);
            Vs[row * VS + d4 * 2]     = pk16(y.x, y.y);
            Vs[row * VS + d4 * 2 + 1] = pk16(y.z, y.w);
        }
        __syncthreads();

        // S = Q @ K^T  (fp16 m16n8k16, 8 k-steps x 8 n-tiles)
        float s[8][4];
        #pragma unroll
        for (int i = 0; i < 8; i++)
            #pragma unroll
            for (int j = 0; j < 4; j++) s[i][j] = 0.f;
        #pragma unroll
        for (int ks = 0; ks < 8; ks++) {
            const int kp = ks * 8 + (lane & 3);
            unsigned a[4];
            a[0] = Qs[r0 * QS + kp];       a[1] = Qs[(r0 + 8) * QS + kp];
            a[2] = Qs[r0 * QS + kp + 4];   a[3] = Qs[(r0 + 8) * QS + kp + 4];
            #pragma unroll
            for (int nt = 0; nt < 8; nt++) {
                int bn = nt * 8 + (lane >> 2);
                mmaf(s[nt], a, Ks[bn * KS + kp], Ks[bn * KS + kp + 4]);
            }
        }
        // online softmax
        const float sc = 0.08838834764831845f;
        float rm0 = -1e30f, rm1 = -1e30f;
        #pragma unroll
        for (int nt = 0; nt < 8; nt++) {
            s[nt][0] *= sc; s[nt][1] *= sc; s[nt][2] *= sc; s[nt][3] *= sc;
            rm0 = fmaxf(rm0, fmaxf(s[nt][0], s[nt][1]));
            rm1 = fmaxf(rm1, fmaxf(s[nt][2], s[nt][3]));
        }
        rm0 = fmaxf(rm0, __shfl_xor_sync(0xffffffffu, rm0, 1));
        rm0 = fmaxf(rm0, __shfl_xor_sync(0xffffffffu, rm0, 2));
        rm1 = fmaxf(rm1, __shfl_xor_sync(0xffffffffu, rm1, 1));
        rm1 = fmaxf(rm1, __shfl_xor_sync(0xffffffffu, rm1, 2));
        float mn0 = fmaxf(m0, rm0), mn1 = fmaxf(m1, rm1);
        float al0 = __expf(m0 - mn0), al1 = __expf(m1 - mn1);
        float rs0 = 0.f, rs1 = 0.f;
        #pragma unroll
        for (int nt = 0; nt < 8; nt++) {
            s[nt][0] = __expf(s[nt][0] - mn0); s[nt][1] = __expf(s[nt][1] - mn0);
            s[nt][2] = __expf(s[nt][2] - mn1); s[nt][3] = __expf(s[nt][3] - mn1);
            rs0 += s[nt][0] + s[nt][1];
            rs1 += s[nt][2] + s[nt][3];
        }
        rs0 += __shfl_xor_sync(0xffffffffu, rs0, 1);
        rs0 += __shfl_xor_sync(0xffffffffu, rs0, 2);
        rs1 += __shfl_xor_sync(0xffffffffu, rs1, 1);
        rs1 += __shfl_xor_sync(0xffffffffu, rs1, 2);
        l0 = l0 * al0 + rs0; l1 = l1 * al1 + rs1;
        m0 = mn0; m1 = mn1;
        #pragma unroll
        for (int nt = 0; nt < 16; nt++) {
            O[nt][0] *= al0; O[nt][1] *= al0; O[nt][2] *= al1; O[nt][3] *= al1;
        }
        // P -> smem packed fp16
        #pragma unroll
        for (int nt = 0; nt < 8; nt++) {
            int pc = nt * 4 + (lane & 3);
            Ps[r0 * PS + pc]       = pk16(s[nt][0], s[nt][1]);
            Ps[(r0 + 8) * PS + pc] = pk16(s[nt][2], s[nt][3]);
        }
        __syncwarp();
        // O += P @ V  (fp16 m16n8k16, 4 k-steps x 8 n16-groups, ldmatrix.trans V)
        #pragma unroll
        for (int ks = 0; ks < 4; ks++) {
            const int kp = ks * 8 + (lane & 3);
            unsigned a[4];
            a[0] = Ps[r0 * PS + kp];       a[1] = Ps[(r0 + 8) * PS + kp];
            a[2] = Ps[r0 * PS + kp + 4];   a[3] = Ps[(r0 + 8) * PS + kp + 4];
            #pragma unroll
            for (int p = 0; p < 8; p++) {
                unsigned bh[4];
                LDSM4T(bh[0], bh[1], bh[2], bh[3], vB + ks * (16 * VS * 4) + p * 32);
                mmaf(O[p * 2],     a, bh[0], bh[1]);
                mmaf(O[p * 2 + 1], a, bh[2], bh[3]);
            }
        }
    }
    // epilogue: normalize + write packed fp16 plane
    const float i0 = 1.f / l0, i1 = 1.f / l1;
    const int tok0 = qb + r0;
    #pragma unroll
    for (int nt = 0; nt < 16; nt++) {
        int cp = h * (HD / 2) + nt * 4 + (lane & 3);
        of[(size_t)tok0 * (DIMW / 2) + cp]       = pk16(O[nt][0] * i0, O[nt][1] * i0);
        of[(size_t)(tok0 + 8) * (DIMW / 2) + cp] = pk16(O[nt][2] * i1, O[nt][3] * i1);
    }
}

extern "C" void kernel_launch(void* const* d_in, const int* in_sizes, int n_in,
                              void* d_out, int out_size) {
    const float* hs  = (const float*)d_in[0];
    const float* enc = (const float*)d_in[1];
    const float* rc  = (const float*)d_in[2];
    const float* rs  = (const float*)d_in[3];
    const float* wq  = (const float*)d_in[4];
    const float* bq  = (const float*)d_in[5];
    const float* wk  = (const float*)d_in[6];
    const float* bk  = (const float*)d_in[7];
    const float* wv  = (const float*)d_in[8];
    const float* bv  = (const float*)d_in[9];
    const float* waq = (const float*)d_in[10];
    const float* baq = (const float*)d_in[11];
    const float* wak = (const float*)d_in[12];
    const float* bak = (const float*)d_in[13];
    const float* wav = (const float*)d_in[14];
    const float* bav = (const float*)d_in[15];
    const float* nq  = (const float*)d_in[16];
    const float* nk  = (const float*)d_in[17];
    const float* naq = (const float*)d_in[18];
    const float* nak = (const float*)d_in[19];
    const float* wo  = (const float*)d_in[20];
    const float* bo  = (const float*)d_in[21];
    const float* wao = (const float*)d_in[22];
    const float* bao = (const float*)d_in[23];
    float* out = (float*)d_out;

    float *qp, *kp, *vp;
    unsigned *afp, *wfp;
    cudaGetSymbolAddress((void**)&qp, g_q);
    cudaGetSymbolAddress((void**)&kp, g_k);
    cudaGetSymbolAddress((void**)&vp, g_v);
    cudaGetSymbolAddress((void**)&afp, g_af);
    cudaGetSymbolAddress((void**)&wfp, g_wf);

    cudaFuncSetAttribute(flash, cudaFuncAttributeMaxDynamicSharedMemorySize, FLASH_SMEM);
    cudaFuncSetAttribute(gemm_f16, cudaFuncAttributeMaxDynamicSharedMemorySize, GEMM_SMEM);

    const size_t WP = (size_t)WELTS / 2;
    const size_t AROW = DIMW / 2;

    // 0) weights (one batched launch; order wq wk wv waq wak wav wo wao)
    {
        WSrc ws;
        ws.p[0] = wq; ws.p[1] = wk; ws.p[2] = wv; ws.p[3] = waq;
        ws.p[4] = wak; ws.p[5] = wav; ws.p[6] = wo; ws.p[7] = wao;
        wconv_all<<<dim3(96, 96, 8), 256>>>(ws, wfp);
    }
    // 1-2) activations: rows [0,512)=enc, [512,2560)=hs
    convf<<<TXT_N * DIMW / 4 / 256, 256>>>(enc, afp, TXT_N * DIMW / 4);
    convf<<<SHID_N * DIMW / 4 / 256, 256>>>(hs, afp + TXT_N * AROW, SHID_N * DIMW / 4);

    // 3) Q projection  (launch idx 3 — ncu capture lands on 3 or 4: both GEMM)
    {
        GemmArgs ga;
        ga.A = afp;
        ga.w[0].B_a = wfp + 3ull * WP; ga.w[0].bias_a = baq; ga.w[0].C_a = qp;
        ga.w[0].B_b = wfp;            ga.w[0].bias_b = bq;
        ga.w[0].C_b = qp + (size_t)TXT_N * DIMW;
        ga.w[1] = ga.w[0]; ga.w[2] = ga.w[0];
        gemm_f16<<<dim3(24, 10, 1), 512, GEMM_SMEM>>>(ga);
    }
    // 4) K+V projections
    {
        GemmArgs ga;
        ga.A = afp;
        ga.w[0].B_a = wfp + 4ull * WP; ga.w[0].bias_a = bak; ga.w[0].C_a = kp;
        ga.w[0].B_b = wfp + 1ull * WP; ga.w[0].bias_b = bk;
        ga.w[0].C_b = kp + (size_t)TXT_N * DIMW;
        ga.w[1].B_a = wfp + 5ull * WP; ga.w[1].bias_a = bav; ga.w[1].C_a = vp;
        ga.w[1].B_b = wfp + 2ull * WP; ga.w[1].bias_b = bv;
        ga.w[1].C_b = vp + (size_t)TXT_N * DIMW;
        ga.w[2] = ga.w[1];
        gemm_f16<<<dim3(24, 10, 2), 512, GEMM_SMEM>>>(ga);
    }

    // 5) norm + rope
    norm_rope<<<STOT_N * NH / 4, 128>>>(qp, kp, nq, nk, naq, nak, rc, rs);

    // 6) flash (writes packed fp16 plane directly)
    flash<<<dim3(STOT_N / 64, NH), 128, FLASH_SMEM>>>(qp, kp, vp, afp);

    // 7) fused out projection
    {
        GemmArgs ga;
        ga.A = afp;
        ga.w[0].B_a = wfp + 7ull * WP; ga.w[0].bias_a = bao;
        ga.w[0].C_a = out + (size_t)SHID_N * DIMW;
        ga.w[0].B_b = wfp + 6ull * WP; ga.w[0].bias_b = bo;
        ga.w[0].C_b = out;
        ga.w[1] = ga.w[0]; ga.w[2] = ga.w[0];
        gemm_f16<<<dim3(24, 10, 1), 512, GEMM_SMEM>>>(ga);
    }
}

// round 11
// speedup vs baseline: 6.0466x; 1.1425x over previous
#include <cuda_runtime.h>
#include <cuda_fp16.h>
#include <math.h>

#define DIMW 3072
#define NH 24
#define HD 128
#define TXT_N 512
#define REF_N 512
#define STOT_N 2560
#define SHID_N 2048
#define WELTS (DIMW * DIMW)

// ---- scratch (device globals; no allocations allowed) ----
__device__ float g_q[STOT_N * DIMW];
__device__ float g_k[STOT_N * DIMW];
__device__ float g_v[STOT_N * DIMW];
// packed fp16 planes (2 fp16 per u32)
__device__ unsigned g_af[STOT_N * DIMW / 2];
__device__ unsigned g_wf[8ull * WELTS / 2];

// ---- helpers ----
__device__ __forceinline__ unsigned pk16(float a, float b) {   // a -> low half
    __half2 h = __floats2half2_rn(a, b);
    return *(unsigned*)&h;
}
__device__ __forceinline__ void mmaf(float* c, const unsigned* a, unsigned b0, unsigned b1) {
    asm volatile("mma.sync.aligned.m16n8k16.row.col.f32.f16.f16.f32 "
        "{%0,%1,%2,%3}, {%4,%5,%6,%7}, {%8,%9}, {%0,%1,%2,%3};\n"
        : "+f"(c[0]), "+f"(c[1]), "+f"(c[2]), "+f"(c[3])
        : "r"(a[0]), "r"(a[1]), "r"(a[2]), "r"(a[3]), "r"(b0), "r"(b1));
}
__device__ __forceinline__ void cpa16(unsigned saddr, const void* g) {
    asm volatile("cp.async.ca.shared.global [%0], [%1], 16;\n" :: "r"(saddr), "l"(g));
}
#define LDSM4(r0,r1,r2,r3,addr) \
    asm volatile("ldmatrix.sync.aligned.m8n8.x4.shared.b16 {%0,%1,%2,%3},[%4];" \
        : "=r"(r0),"=r"(r1),"=r"(r2),"=r"(r3) : "r"(addr))
#define LDSM4T(r0,r1,r2,r3,addr) \
    asm volatile("ldmatrix.sync.aligned.m8n8.x4.trans.shared.b16 {%0,%1,%2,%3},[%4];" \
        : "=r"(r0),"=r"(r1),"=r"(r2),"=r"(r3) : "r"(addr))

// ============================================================================
// fp32 -> packed fp16 plane
// ============================================================================
__global__ void __launch_bounds__(256) convf(const float* __restrict__ s,
        unsigned* __restrict__ d, int n4)
{
    int i = blockIdx.x * 256 + threadIdx.x;
    if (i >= n4) return;
    float4 x = ((const float4*)s)[i];
    uint2 H;
    H.x = pk16(x.x, x.y);
    H.y = pk16(x.z, x.w);
    ((uint2*)d)[i] = H;
}

// batched weight convert: 8 weights, z selects
struct WSrc { const float* p[8]; };
__global__ void __launch_bounds__(256) wconv_all(WSrc ws, unsigned* __restrict__ d)
{
    const float* __restrict__ W = ws.p[blockIdx.z];
    size_t base = (size_t)blockIdx.z * (WELTS / 2);
    int i = blockIdx.x * 256 + threadIdx.x + blockIdx.y * (256 * 96);
    float4 x = ((const float4*)W)[i];
    uint2 H;
    H.x = pk16(x.x, x.y);
    H.y = pk16(x.z, x.w);
    ((uint2*)(d + base))[i] = H;
}

// ============================================================================
// fp16 GEMM: C[M,3072] = A @ W + bias, single MMA term.
// BM=128, BN=128, BK=32, 3-stage cp.async, 256 threads = 8 warps (4m x 2n),
// warp tile 32x64, m16n8k16, ldmatrix fragments. 2 CTAs/SM (regs+smem sized).
// Row-range dual weights (txt rows < 512 use set A). blockIdx.z selects op.
// ============================================================================
struct DualW {
    const unsigned* B_a; const float* bias_a; float* C_a;
    const unsigned* B_b; const float* bias_b; float* C_b;
};
struct GemmArgs {
    const unsigned* A;
    DualW w[3];
};

#define BM 128
#define BN 128
#define SA_T (BM * 20)            // 2560 u32/stage, A rows 80B (64 data + 16 pad)
#define SB_T (32 * 68)            // 2176 u32/stage, B rows 272B (256 data + 16 pad)
#define STG4 ((SA_T + SB_T) * 4)  // 18944 B
#define GEMM_SMEM (3 * STG4)      // 56832 B

__global__ void __launch_bounds__(256, 2) gemm_f16(GemmArgs ga)
{
    extern __shared__ unsigned smg[];

    const DualW& w = ga.w[blockIdx.z];
    const int mBase = blockIdx.y * BM;
    const int nBase = blockIdx.x * BN;
    const bool low = (mBase < TXT_N);
    const unsigned* __restrict__ B = low ? w.B_a : w.B_b;
    const float* __restrict__ bias = low ? w.bias_a : w.bias_b;
    float* __restrict__ C = low ? (w.C_a + (size_t)mBase * DIMW)
                                : (w.C_b + (size_t)(mBase - TXT_N) * DIMW);
    const unsigned* __restrict__ A = ga.A;

    const int tid  = threadIdx.x;
    const int lane = tid & 31;
    const int warp = tid >> 5;
    const int wm = warp >> 1;     // 0..3
    const int wn = warp & 1;      // 0..1

    const unsigned smBase = (unsigned)__cvta_generic_to_shared(smg);
    const int quad = lane >> 3;
    const unsigned offA = (unsigned)((wm * 32 + (lane & 7) + (quad & 1) * 8) * 80 + (quad >> 1) * 16);
    const unsigned offB = (unsigned)(((lane & 7) + (quad & 1) * 8) * 272 + (wn * 64 + (quad >> 1) * 8) * 2);

    auto load_stage = [&](int kb, int buf) {
        unsigned base = smBase + buf * STG4;
        #pragma unroll
        for (int i = 0; i < 2; i++) {
            int c = tid + i * 256;               // 512 cpa for A (128 rows x 4 segs)
            int row = c >> 2, seg = c & 3;
            size_t g = (size_t)(mBase + row) * (DIMW / 2) + kb * 16 + seg * 4;
            cpa16(base + row * 80 + seg * 16, A + g);
        }
        #pragma unroll
        for (int i = 0; i < 2; i++) {
            int c = tid + i * 256;               // 512 cpa for B (32 rows x 16 segs)
            int row = c >> 4, seg = c & 15;
            size_t g = (size_t)(kb * 32 + row) * (DIMW / 2) + (nBase >> 1) + seg * 4;
            cpa16(base + SA_T * 4 + row * 272 + seg * 16, B + g);
        }
        asm volatile("cp.async.commit_group;\n");
    };

    float acc[2][8][4];
    #pragma unroll
    for (int i = 0; i < 2; i++)
        #pragma unroll
        for (int j = 0; j < 8; j++)
            #pragma unroll
            for (int p = 0; p < 4; p++) acc[i][j][p] = 0.f;

    const int NK = DIMW / 32;   // 96
    load_stage(0, 0);
    load_stage(1, 1);

    int buf = 0;
    for (int kb = 0; kb < NK; kb++) {
        if (kb + 2 < NK) {
            asm volatile("cp.async.wait_group 1;\n");
        } else {
            asm volatile("cp.async.wait_group 0;\n");
        }
        __syncthreads();
        if (kb + 2 < NK) load_stage(kb + 2, (kb + 2) % 3);

        const unsigned stb = smBase + buf * STG4;
        const unsigned aP = stb + offA;
        const unsigned bP = stb + SA_T * 4 + offB;

        #pragma unroll
        for (int k16 = 0; k16 < 2; k16++) {
            unsigned a[2][4];
            #pragma unroll
            for (int mt = 0; mt < 2; mt++)
                LDSM4(a[mt][0], a[mt][1], a[mt][2], a[mt][3], aP + mt * (16 * 80) + k16 * 32);
            #pragma unroll
            for (int p = 0; p < 4; p++) {
                unsigned bh[4];
                LDSM4T(bh[0], bh[1], bh[2], bh[3], bP + k16 * (16 * 272) + p * 32);
                #pragma unroll
                for (int h = 0; h < 2; h++)
                    #pragma unroll
                    for (int mt = 0; mt < 2; mt++)
                        mmaf(acc[mt][p * 2 + h], a[mt], bh[2 * h], bh[2 * h + 1]);
            }
        }
        buf = (buf + 1) % 3;
    }

    #pragma unroll
    for (int mt = 0; mt < 2; mt++) {
        int r = wm * 32 + mt * 16 + (lane >> 2);
        #pragma unroll
        for (int nt = 0; nt < 8; nt++) {
            int cg = nBase + wn * 64 + nt * 8 + (lane & 3) * 2;
            float b0 = bias[cg], b1 = bias[cg + 1];
            float2 v0 = make_float2(acc[mt][nt][0] + b0, acc[mt][nt][1] + b1);
            float2 v1 = make_float2(acc[mt][nt][2] + b0, acc[mt][nt][3] + b1);
            *(float2*)&C[(size_t)r * DIMW + cg] = v0;
            *(float2*)&C[(size_t)(r + 8) * DIMW + cg] = v1;
        }
    }
}

// ============================================================================
// Fused per-head RMSNorm + interleaved RoPE, in place on q and k (fp32).
// ============================================================================
__global__ void __launch_bounds__(128) norm_rope(float* __restrict__ q, float* __restrict__ k,
        const float* __restrict__ nq, const float* __restrict__ nk,
        const float* __restrict__ naq, const float* __restrict__ nak,
        const float* __restrict__ rc, const float* __restrict__ rs)
{
    const int gw   = blockIdx.x * 4 + (threadIdx.x >> 5);
    const int lane = threadIdx.x & 31;
    const int t = gw / NH, h = gw % NH;
    const size_t base = (size_t)t * DIMW + h * HD + lane * 4;
    const float* wq = (t < TXT_N) ? naq : nq;
    const float* wk = (t < TXT_N) ? nak : nk;
    const float4 c4 = *(const float4*)(rc + (size_t)t * HD + lane * 4);
    const float4 s4 = *(const float4*)(rs + (size_t)t * HD + lane * 4);

    #pragma unroll
    for (int which = 0; which < 2; which++) {
        float* buf = which ? k : q;
        const float* wv = which ? wk : wq;
        float4 x = *(float4*)(buf + base);
        float ss = x.x * x.x + x.y * x.y + x.z * x.z + x.w * x.w;
        ss += __shfl_xor_sync(0xffffffffu, ss, 16);
        ss += __shfl_xor_sync(0xffffffffu, ss, 8);
        ss += __shfl_xor_sync(0xffffffffu, ss, 4);
        ss += __shfl_xor_sync(0xffffffffu, ss, 2);
        ss += __shfl_xor_sync(0xffffffffu, ss, 1);
        float r = rsqrtf(ss * (1.0f / HD) + 1e-6f);
        float4 w4 = *(const float4*)(wv + lane * 4);
        x.x *= r * w4.x; x.y *= r * w4.y; x.z *= r * w4.z; x.w *= r * w4.w;
        float4 y;
        y.x = x.x * c4.x - x.y * s4.x;
        y.y = x.y * c4.y + x.x * s4.y;
        y.z = x.z * c4.z - x.w * s4.z;
        y.w = x.w * c4.w + x.z * s4.w;
        *(float4*)(buf + base) = y;
    }
}

// ============================================================================
// Flash attention, all-fp16 MMA (single term). QK: m16n8k16, PV: m16n8k16 with
// V fragments via ldmatrix.trans. Epilogue writes packed fp16 plane (fused
// convert for the out projection).
// ============================================================================
#define QS 68
#define KS 68
#define VS 68
#define PS 36
#define V_OFF (64 * QS + 64 * KS)            // u32 offset of V
#define P_OFF (V_OFF + 64 * VS)
#define FLASH_SMEM ((P_OFF + 64 * PS) * 4)   // 61440 B

__global__ void __launch_bounds__(128) flash(const float* __restrict__ q,
        const float* __restrict__ k, const float* __restrict__ v,
        unsigned* __restrict__ of)
{
    extern __shared__ unsigned sm[];
    unsigned* Qs = sm;
    unsigned* Ks = Qs + 64 * QS;
    unsigned* Vs = sm + V_OFF;
    unsigned* Ps = sm + P_OFF;
    const unsigned smBase = (unsigned)__cvta_generic_to_shared(sm);

    const int tid = threadIdx.x, lane = tid & 31, w = tid >> 5;
    const int qt = blockIdx.x, h = blockIdx.y;
    const int qb = qt * 64;
    const bool isref = (qb >= TXT_N) && (qb < TXT_N + REF_N);
    const int kv0 = isref ? TXT_N : 0;
    const int nkt = isref ? (REF_N / 64) : (STOT_N / 64);

    // ldmatrix.trans per-lane offset into V (k-rows x n-cols, 272B rows)
    const int quad = lane >> 3;
    const unsigned offV = (unsigned)(((lane & 7) + (quad & 1) * 8) * (VS * 4) + (quad >> 1) * 16);
    const unsigned vB = smBase + V_OFF * 4 + offV;

    // load Q tile 64x128 -> packed fp16
    #pragma unroll
    for (int i = 0; i < 16; i++) {
        int f = tid + i * 128;
        int row = f >> 5, d4 = f & 31;
        float4 x = *(const float4*)(q + (size_t)(qb + row) * DIMW + h * HD + d4 * 4);
        Qs[row * QS + d4 * 2]     = pk16(x.x, x.y);
        Qs[row * QS + d4 * 2 + 1] = pk16(x.z, x.w);
    }

    float O[16][4];
    #pragma unroll
    for (int i = 0; i < 16; i++)
        #pragma unroll
        for (int j = 0; j < 4; j++) O[i][j] = 0.f;
    float m0 = -1e30f, m1 = -1e30f, l0 = 0.f, l1 = 0.f;
    const int r0 = w * 16 + (lane >> 2);

    for (int it = 0; it < nkt; it++) {
        __syncthreads();
        const int kt0 = kv0 + it * 64;
        #pragma unroll
        for (int i = 0; i < 16; i++) {
            int f = tid + i * 128;
            int row = f >> 5, d4 = f & 31;
            float4 x = *(const float4*)(k + (size_t)(kt0 + row) * DIMW + h * HD + d4 * 4);
            Ks[row * KS + d4 * 2]     = pk16(x.x, x.y);
            Ks[row * KS + d4 * 2 + 1] = pk16(x.z, x.w);
            float4 y = *(const float4*)(v + (size_t)(kt0 + row) * DIMW + h * HD + d4 * 4);
            Vs[row * VS + d4 * 2]     = pk16(y.x, y.y);
            Vs[row * VS + d4 * 2 + 1] = pk16(y.z, y.w);
        }
        __syncthreads();

        // S = Q @ K^T  (fp16 m16n8k16, 8 k-steps x 8 n-tiles)
        float s[8][4];
        #pragma unroll
        for (int i = 0; i < 8; i++)
            #pragma unroll
            for (int j = 0; j < 4; j++) s[i][j] = 0.f;
        #pragma unroll
        for (int ks = 0; ks < 8; ks++) {
            const int kp = ks * 8 + (lane & 3);
            unsigned a[4];
            a[0] = Qs[r0 * QS + kp];       a[1] = Qs[(r0 + 8) * QS + kp];
            a[2] = Qs[r0 * QS + kp + 4];   a[3] = Qs[(r0 + 8) * QS + kp + 4];
            #pragma unroll
            for (int nt = 0; nt < 8; nt++) {
                int bn = nt * 8 + (lane >> 2);
                mmaf(s[nt], a, Ks[bn * KS + kp], Ks[bn * KS + kp + 4]);
            }
        }
        // online softmax
        const float sc = 0.08838834764831845f;
        float rm0 = -1e30f, rm1 = -1e30f;
        #pragma unroll
        for (int nt = 0; nt < 8; nt++) {
            s[nt][0] *= sc; s[nt][1] *= sc; s[nt][2] *= sc; s[nt][3] *= sc;
            rm0 = fmaxf(rm0, fmaxf(s[nt][0], s[nt][1]));
            rm1 = fmaxf(rm1, fmaxf(s[nt][2], s[nt][3]));
        }
        rm0 = fmaxf(rm0, __shfl_xor_sync(0xffffffffu, rm0, 1));
        rm0 = fmaxf(rm0, __shfl_xor_sync(0xffffffffu, rm0, 2));
        rm1 = fmaxf(rm1, __shfl_xor_sync(0xffffffffu, rm1, 1));
        rm1 = fmaxf(rm1, __shfl_xor_sync(0xffffffffu, rm1, 2));
        float mn0 = fmaxf(m0, rm0), mn1 = fmaxf(m1, rm1);
        float al0 = __expf(m0 - mn0), al1 = __expf(m1 - mn1);
        float rs0 = 0.f, rs1 = 0.f;
        #pragma unroll
        for (int nt = 0; nt < 8; nt++) {
            s[nt][0] = __expf(s[nt][0] - mn0); s[nt][1] = __expf(s[nt][1] - mn0);
            s[nt][2] = __expf(s[nt][2] - mn1); s[nt][3] = __expf(s[nt][3] - mn1);
            rs0 += s[nt][0] + s[nt][1];
            rs1 += s[nt][2] + s[nt][3];
        }
        rs0 += __shfl_xor_sync(0xffffffffu, rs0, 1);
        rs0 += __shfl_xor_sync(0xffffffffu, rs0, 2);
        rs1 += __shfl_xor_sync(0xffffffffu, rs1, 1);
        rs1 += __shfl_xor_sync(0xffffffffu, rs1, 2);
        l0 = l0 * al0 + rs0; l1 = l1 * al1 + rs1;
        m0 = mn0; m1 = mn1;
        #pragma unroll
        for (int nt = 0; nt < 16; nt++) {
            O[nt][0] *= al0; O[nt][1] *= al0; O[nt][2] *= al1; O[nt][3] *= al1;
        }
        // P -> smem packed fp16
        #pragma unroll
        for (int nt = 0; nt < 8; nt++) {
            int pc = nt * 4 + (lane & 3);
            Ps[r0 * PS + pc]       = pk16(s[nt][0], s[nt][1]);
            Ps[(r0 + 8) * PS + pc] = pk16(s[nt][2], s[nt][3]);
        }
        __syncwarp();
        // O += P @ V  (fp16 m16n8k16, 4 k-steps x 8 n16-groups, ldmatrix.trans V)
        #pragma unroll
        for (int ks = 0; ks < 4; ks++) {
            const int kp = ks * 8 + (lane & 3);
            unsigned a[4];
            a[0] = Ps[r0 * PS + kp];       a[1] = Ps[(r0 + 8) * PS + kp];
            a[2] = Ps[r0 * PS + kp + 4];   a[3] = Ps[(r0 + 8) * PS + kp + 4];
            #pragma unroll
            for (int p = 0; p < 8; p++) {
                unsigned bh[4];
                LDSM4T(bh[0], bh[1], bh[2], bh[3], vB + ks * (16 * VS * 4) + p * 32);
                mmaf(O[p * 2],     a, bh[0], bh[1]);
                mmaf(O[p * 2 + 1], a, bh[2], bh[3]);
            }
        }
    }
    // epilogue: normalize + write packed fp16 plane
    const float i0 = 1.f / l0, i1 = 1.f / l1;
    const int tok0 = qb + r0;
    #pragma unroll
    for (int nt = 0; nt < 16; nt++) {
        int cp = h * (HD / 2) + nt * 4 + (lane & 3);
        of[(size_t)tok0 * (DIMW / 2) + cp]       = pk16(O[nt][0] * i0, O[nt][1] * i0);
        of[(size_t)(tok0 + 8) * (DIMW / 2) + cp] = pk16(O[nt][2] * i1, O[nt][3] * i1);
    }
}

extern "C" void kernel_launch(void* const* d_in, const int* in_sizes, int n_in,
                              void* d_out, int out_size) {
    const float* hs  = (const float*)d_in[0];
    const float* enc = (const float*)d_in[1];
    const float* rc  = (const float*)d_in[2];
    const float* rs  = (const float*)d_in[3];
    const float* wq  = (const float*)d_in[4];
    const float* bq  = (const float*)d_in[5];
    const float* wk  = (const float*)d_in[6];
    const float* bk  = (const float*)d_in[7];
    const float* wv  = (const float*)d_in[8];
    const float* bv  = (const float*)d_in[9];
    const float* waq = (const float*)d_in[10];
    const float* baq = (const float*)d_in[11];
    const float* wak = (const float*)d_in[12];
    const float* bak = (const float*)d_in[13];
    const float* wav = (const float*)d_in[14];
    const float* bav = (const float*)d_in[15];
    const float* nq  = (const float*)d_in[16];
    const float* nk  = (const float*)d_in[17];
    const float* naq = (const float*)d_in[18];
    const float* nak = (const float*)d_in[19];
    const float* wo  = (const float*)d_in[20];
    const float* bo  = (const float*)d_in[21];
    const float* wao = (const float*)d_in[22];
    const float* bao = (const float*)d_in[23];
    float* out = (float*)d_out;

    float *qp, *kp, *vp;
    unsigned *afp, *wfp;
    cudaGetSymbolAddress((void**)&qp, g_q);
    cudaGetSymbolAddress((void**)&kp, g_k);
    cudaGetSymbolAddress((void**)&vp, g_v);
    cudaGetSymbolAddress((void**)&afp, g_af);
    cudaGetSymbolAddress((void**)&wfp, g_wf);

    cudaFuncSetAttribute(flash, cudaFuncAttributeMaxDynamicSharedMemorySize, FLASH_SMEM);
    cudaFuncSetAttribute(gemm_f16, cudaFuncAttributeMaxDynamicSharedMemorySize, GEMM_SMEM);

    const size_t WP = (size_t)WELTS / 2;
    const size_t AROW = DIMW / 2;

    // 0) weights (one batched launch; order wq wk wv waq wak wav wo wao)
    {
        WSrc ws;
        ws.p[0] = wq; ws.p[1] = wk; ws.p[2] = wv; ws.p[3] = waq;
        ws.p[4] = wak; ws.p[5] = wav; ws.p[6] = wo; ws.p[7] = wao;
        wconv_all<<<dim3(96, 96, 8), 256>>>(ws, wfp);
    }
    // 1-2) activations: rows [0,512)=enc, [512,2560)=hs
    convf<<<TXT_N * DIMW / 4 / 256, 256>>>(enc, afp, TXT_N * DIMW / 4);
    convf<<<SHID_N * DIMW / 4 / 256, 256>>>(hs, afp + TXT_N * AROW, SHID_N * DIMW / 4);

    // 3) fused QKV projection: grid (24, 20, 3) = 1440 CTAs, 2 CTAs/SM
    {
        GemmArgs ga;
        ga.A = afp;
        ga.w[0].B_a = wfp + 3ull * WP; ga.w[0].bias_a = baq; ga.w[0].C_a = qp;
        ga.w[0].B_b = wfp;            ga.w[0].bias_b = bq;
        ga.w[0].C_b = qp + (size_t)TXT_N * DIMW;
        ga.w[1].B_a = wfp + 4ull * WP; ga.w[1].bias_a = bak; ga.w[1].C_a = kp;
        ga.w[1].B_b = wfp + 1ull * WP; ga.w[1].bias_b = bk;
        ga.w[1].C_b = kp + (size_t)TXT_N * DIMW;
        ga.w[2].B_a = wfp + 5ull * WP; ga.w[2].bias_a = bav; ga.w[2].C_a = vp;
        ga.w[2].B_b = wfp + 2ull * WP; ga.w[2].bias_b = bv;
        ga.w[2].C_b = vp + (size_t)TXT_N * DIMW;
        gemm_f16<<<dim3(24, 20, 3), 256, GEMM_SMEM>>>(ga);
    }

    // 4) norm + rope
    norm_rope<<<STOT_N * NH / 4, 128>>>(qp, kp, nq, nk, naq, nak, rc, rs);

    // 5) flash (writes packed fp16 plane directly)
    flash<<<dim3(STOT_N / 64, NH), 128, FLASH_SMEM>>>(qp, kp, vp, afp);

    // 6) fused out projection: grid (24, 20)
    {
        GemmArgs ga;
        ga.A = afp;
        ga.w[0].B_a = wfp + 7ull * WP; ga.w[0].bias_a = bao;
        ga.w[0].C_a = out + (size_t)SHID_N * DIMW;
        ga.w[0].B_b = wfp + 6ull * WP; ga.w[0].bias_b = bo;
        ga.w[0].C_b = out;
        ga.w[1] = ga.w[0]; ga.w[2] = ga.w[0];
        gemm_f16<<<dim3(24, 20, 1), 256, GEMM_SMEM>>>(ga);
    }
}